// round 1
// baseline (speedup 1.0000x reference)
#include <cuda_runtime.h>
#include <cuda_bf16.h>
#include <math.h>

// ---------------------------------------------------------------------------
// MLA forward, fp32 baseline.
// Pipeline:
//  1. qa = x @ wq_a                    (2048 x 4096 x 1536)
//  2. qa = rmsnorm(qa) * q_norm_w
//  3. q  = qa @ wq_b                   (2048 x 1536 x 6144)   q[s, h*192+d]
//  4. kv = x @ wkv_a                   (2048 x 4096 x 576)
//  5. kf[:,0:512]   = rmsnorm(kv[:,0:512]) * kv_norm_w
//     kf[:,512:576] = rope(kv[:,512:576])
//  6. qf[(s,h),512:576] = rope(q[s, h*192+128 : h*192+192])
//  7. qf[(s,h),0:512]   = q_nope @ wkv_b[h,:128,:]   (batched over h)
//  8. scores[b] = qf[b] @ kf[b]^T      (32768 x 576 x 1024, per b)
//  9. softmax(scores*SCALE + mask[s,:])
// 10. oc[b] = probs @ kf[b][:,0:512]   (32768 x 1024 x 512)
// 11. ov[s, h*128+d] = oc[(s,h),:] @ wkv_b[h,128:,:]^T  (batched over h)
// 12. out = ov @ wo                    (2048 x 4096 x 4096)
// ---------------------------------------------------------------------------

static constexpr int BM = 128, BN = 128, BK = 8, PADW = 132;

// scratch (device globals; allocation-free rule)
__device__ __align__(256) float g_qa[2048L * 1536];
__device__ __align__(256) float g_q [2048L * 6144];
__device__ __align__(256) float g_kv[2048L * 576];
__device__ __align__(256) float g_kf[2048L * 576];
__device__ __align__(256) float g_qf[2048L * 32 * 576];
__device__ __align__(256) float g_sc[2L * 32768 * 1024];
__device__ __align__(256) float g_oc[2048L * 32 * 512];
__device__ __align__(256) float g_ov[2048L * 4096];

// ---------------------------------------------------------------------------
// Generic tiled SGEMM. A is M x K row-major (lda). If !TB: B is K x N (ldb).
// If TB: B is N x K (ldb), i.e. C = A * B^T.  C is M x N (ldc).
// z = blockIdx.z batch, with element offsets sA/sB/sC.
// Requirements: M % 128 == 0, K % 8 == 0, all ld* % 4 == 0, offsets % 4 == 0.
// N may be arbitrary (guarded).
// ---------------------------------------------------------------------------
template <bool TB>
__global__ __launch_bounds__(256) void sgemm(
    const float* __restrict__ A, const float* __restrict__ B,
    float* __restrict__ C, int M, int N, int K,
    int lda, int ldb, int ldc, long sA, long sB, long sC)
{
    __shared__ float As[BK][PADW];
    __shared__ float Bs[BK][PADW];
    A += (long)blockIdx.z * sA;
    B += (long)blockIdx.z * sB;
    C += (long)blockIdx.z * sC;
    const int n0 = blockIdx.x * BN;
    const int m0 = blockIdx.y * BM;
    const int tid = threadIdx.x;
    const int tx = tid & 15, ty = tid >> 4;

    const int arow = tid >> 1;          // 0..127
    const int acol = (tid & 1) * 4;     // 0 or 4
    const int brow = tid >> 5;          // 0..7   (!TB B load)
    const int bcol = (tid & 31) * 4;    // 0..124 (!TB B load)

    float acc[8][8];
#pragma unroll
    for (int i = 0; i < 8; i++)
#pragma unroll
        for (int j = 0; j < 8; j++) acc[i][j] = 0.f;

    const float* Ap = A + (long)(m0 + arow) * lda + acol;

    for (int k0 = 0; k0 < K; k0 += BK) {
        // A tile: 128 rows x 8 k, float4 per thread (M,K multiples guaranteed)
        float4 av = *reinterpret_cast<const float4*>(Ap + k0);
        As[acol + 0][arow] = av.x;
        As[acol + 1][arow] = av.y;
        As[acol + 2][arow] = av.z;
        As[acol + 3][arow] = av.w;
        if (!TB) {
            int n = n0 + bcol;
            const float* Bp = B + (long)(k0 + brow) * ldb;
            float4 bv;
            if (n + 3 < N) {
                bv = *reinterpret_cast<const float4*>(Bp + n);
            } else {
                bv.x = (n + 0 < N) ? Bp[n + 0] : 0.f;
                bv.y = (n + 1 < N) ? Bp[n + 1] : 0.f;
                bv.z = (n + 2 < N) ? Bp[n + 2] : 0.f;
                bv.w = (n + 3 < N) ? Bp[n + 3] : 0.f;
            }
            *reinterpret_cast<float4*>(&Bs[brow][bcol]) = bv;
        } else {
            int n = n0 + arow;
            float4 bv = make_float4(0.f, 0.f, 0.f, 0.f);
            if (n < N)
                bv = *reinterpret_cast<const float4*>(B + (long)n * ldb + k0 + acol);
            Bs[acol + 0][arow] = bv.x;
            Bs[acol + 1][arow] = bv.y;
            Bs[acol + 2][arow] = bv.z;
            Bs[acol + 3][arow] = bv.w;
        }
        __syncthreads();
#pragma unroll
        for (int k = 0; k < BK; k++) {
            float a[8], b[8];
            *reinterpret_cast<float4*>(&a[0]) = *reinterpret_cast<const float4*>(&As[k][ty * 8]);
            *reinterpret_cast<float4*>(&a[4]) = *reinterpret_cast<const float4*>(&As[k][ty * 8 + 4]);
            *reinterpret_cast<float4*>(&b[0]) = *reinterpret_cast<const float4*>(&Bs[k][tx * 8]);
            *reinterpret_cast<float4*>(&b[4]) = *reinterpret_cast<const float4*>(&Bs[k][tx * 8 + 4]);
#pragma unroll
            for (int i = 0; i < 8; i++)
#pragma unroll
                for (int j = 0; j < 8; j++)
                    acc[i][j] = fmaf(a[i], b[j], acc[i][j]);
        }
        __syncthreads();
    }
#pragma unroll
    for (int i = 0; i < 8; i++) {
        float* Cp = C + (long)(m0 + ty * 8 + i) * ldc;
#pragma unroll
        for (int j = 0; j < 8; j += 4) {
            int n = n0 + tx * 8 + j;
            if (n + 3 < N) {
                float4 v = make_float4(acc[i][j], acc[i][j + 1], acc[i][j + 2], acc[i][j + 3]);
                *reinterpret_cast<float4*>(Cp + n) = v;
            } else {
#pragma unroll
                for (int jj = 0; jj < 4; jj++)
                    if (n + jj < N) Cp[n + jj] = acc[i][j + jj];
            }
        }
    }
}

// ---------------------------------------------------------------------------
// block reduce (sum or max); sh must have >= 32 floats
// ---------------------------------------------------------------------------
template <bool IS_MAX>
__device__ __forceinline__ float block_reduce(float v, float* sh)
{
    __syncthreads();  // protect sh reuse across successive calls
#pragma unroll
    for (int o = 16; o; o >>= 1) {
        float t = __shfl_xor_sync(0xffffffffu, v, o);
        v = IS_MAX ? fmaxf(v, t) : v + t;
    }
    const int lane = threadIdx.x & 31, w = threadIdx.x >> 5;
    if (lane == 0) sh[w] = v;
    __syncthreads();
    const int nw = blockDim.x >> 5;
    if (w == 0) {
        v = (lane < nw) ? sh[lane] : (IS_MAX ? -INFINITY : 0.f);
#pragma unroll
        for (int o = 16; o; o >>= 1) {
            float t = __shfl_xor_sync(0xffffffffu, v, o);
            v = IS_MAX ? fmaxf(v, t) : v + t;
        }
        if (lane == 0) sh[0] = v;
    }
    __syncthreads();
    return sh[0];
}

// ---------------------------------------------------------------------------
// rmsnorm over `width` elements per row
// ---------------------------------------------------------------------------
__global__ void rmsnorm_kernel(const float* __restrict__ in, const float* __restrict__ w,
                               float* __restrict__ out, int width, int ldin, int ldout)
{
    __shared__ float sh[32];
    const long row = blockIdx.x;
    const float* x = in + row * ldin;
    float* y = out + row * ldout;
    float ss = 0.f;
    for (int i = threadIdx.x; i < width; i += blockDim.x) {
        float v = x[i];
        ss += v * v;
    }
    float tot = block_reduce<false>(ss, sh);
    float rinv = rsqrtf(tot / (float)width + 1e-6f);
    for (int i = threadIdx.x; i < width; i += blockDim.x)
        y[i] = x[i] * rinv * w[i];
}

// rope for k_pe: kv[t, 512:576] -> kf[t, 512:576]; pos = t % 1024
__global__ void rope_k(const float* __restrict__ kv, const float* __restrict__ fc,
                       float* __restrict__ kf)
{
    int idx = blockIdx.x * blockDim.x + threadIdx.x;  // 2048*32
    int t = idx >> 5, i = idx & 31;
    int pos = t & 1023;
    float c = fc[(pos * 32 + i) * 2 + 0];
    float s = fc[(pos * 32 + i) * 2 + 1];
    float xe = kv[(long)t * 576 + 512 + 2 * i];
    float xo = kv[(long)t * 576 + 513 + 2 * i];
    kf[(long)t * 576 + 512 + 2 * i] = xe * c - xo * s;
    kf[(long)t * 576 + 513 + 2 * i] = xe * s + xo * c;
}

// rope for q_pe: q[r, h*192+128 .. +192] -> qf[(r*32+h), 512:576]
__global__ void rope_q(const float* __restrict__ q, const float* __restrict__ fc,
                       float* __restrict__ qf)
{
    long idx = (long)blockIdx.x * blockDim.x + threadIdx.x;  // 2048*32*32
    int i = idx & 31;
    int h = (idx >> 5) & 31;
    long r = idx >> 10;
    int pos = (int)(r & 1023);
    const float* src = q + r * 6144 + h * 192 + 128 + 2 * i;
    float xe = src[0], xo = src[1];
    float c = fc[(pos * 32 + i) * 2 + 0];
    float s = fc[(pos * 32 + i) * 2 + 1];
    float* dst = qf + (r * 32 + h) * 576 + 512 + 2 * i;
    dst[0] = xe * c - xo * s;
    dst[1] = xe * s + xo * c;
}

// softmax over 1024 cols of one row; applies SCALE and mask[s, :]
__global__ __launch_bounds__(256) void softmax_kernel(float* __restrict__ sc,
                                                      const float* __restrict__ mask)
{
    __shared__ float sh[32];
    const long m = blockIdx.x;                 // 0..65535
    const int srow = (int)((m & 32767) >> 5);  // query position s
    float* p = sc + m * 1024;
    const float* mk = mask + (long)srow * 1024;
    const float scale = 0.07216878364870322f;  // 192^-0.5
    const int tid = threadIdx.x;
    float l[4];
    float mx = -INFINITY;
#pragma unroll
    for (int j = 0; j < 4; j++) {
        int t = tid + j * 256;
        l[j] = p[t] * scale + mk[t];
        mx = fmaxf(mx, l[j]);
    }
    float M = block_reduce<true>(mx, sh);
    float s = 0.f;
#pragma unroll
    for (int j = 0; j < 4; j++) {
        l[j] = expf(l[j] - M);
        s += l[j];
    }
    float S = block_reduce<false>(s, sh);
    float inv = 1.f / S;
#pragma unroll
    for (int j = 0; j < 4; j++) p[tid + j * 256] = l[j] * inv;
}

// ---------------------------------------------------------------------------
extern "C" void kernel_launch(void* const* d_in, const int* in_sizes, int n_in,
                              void* d_out, int out_size)
{
    const float* x        = (const float*)d_in[0];  // [2,1024,4096]
    const float* fc       = (const float*)d_in[1];  // [1024,32,2]
    const float* mask     = (const float*)d_in[2];  // [1024,1024]
    const float* wq_a     = (const float*)d_in[3];  // [4096,1536]
    const float* q_norm_w = (const float*)d_in[4];  // [1536]
    const float* wq_b     = (const float*)d_in[5];  // [1536,6144]
    const float* wkv_a    = (const float*)d_in[6];  // [4096,576]
    const float* kv_norm_w= (const float*)d_in[7];  // [512]
    const float* wkv_b    = (const float*)d_in[8];  // [32,256,512]
    const float* wo       = (const float*)d_in[9];  // [4096,4096]
    float* out = (float*)d_out;                     // [2,1024,4096]

    float *qa, *q, *kv, *kf, *qf, *sc, *oc, *ov;
    cudaGetSymbolAddress((void**)&qa, g_qa);
    cudaGetSymbolAddress((void**)&q,  g_q);
    cudaGetSymbolAddress((void**)&kv, g_kv);
    cudaGetSymbolAddress((void**)&kf, g_kf);
    cudaGetSymbolAddress((void**)&qf, g_qf);
    cudaGetSymbolAddress((void**)&sc, g_sc);
    cudaGetSymbolAddress((void**)&oc, g_oc);
    cudaGetSymbolAddress((void**)&ov, g_ov);

    const dim3 blk(256);

    // 1. qa = x @ wq_a
    sgemm<false><<<dim3(12, 16, 1), blk>>>(x, wq_a, qa, 2048, 1536, 4096,
                                           4096, 1536, 1536, 0, 0, 0);
    // 2. rmsnorm qa (in-place)
    rmsnorm_kernel<<<2048, 256>>>(qa, q_norm_w, qa, 1536, 1536, 1536);
    // 3. q = qa @ wq_b
    sgemm<false><<<dim3(48, 16, 1), blk>>>(qa, wq_b, q, 2048, 6144, 1536,
                                           1536, 6144, 6144, 0, 0, 0);
    // 4. kv = x @ wkv_a
    sgemm<false><<<dim3(5, 16, 1), blk>>>(x, wkv_a, kv, 2048, 576, 4096,
                                          4096, 576, 576, 0, 0, 0);
    // 5. k_full: rmsnorm + rope
    rmsnorm_kernel<<<2048, 256>>>(kv, kv_norm_w, kf, 512, 576, 576);
    rope_k<<<256, 256>>>(kv, fc, kf);
    // 6. q_pe rope -> qf cols 512..575
    rope_q<<<2048, 1024>>>(q, fc, qf);
    // 7. q absorb: qf[(s,h),0:512] = q_nope[s,h,:] @ wkv_b[h,:128,:]  (z = h)
    sgemm<false><<<dim3(4, 16, 32), blk>>>(q, wkv_b, qf, 2048, 512, 128,
                                           6144, 512, 32 * 576,
                                           192, 256L * 512, 576);
    // 8. scores[b] = qf[b] @ kf[b]^T  (z = b)
    sgemm<true><<<dim3(8, 256, 2), blk>>>(qf, kf, sc, 32768, 1024, 576,
                                          576, 576, 1024,
                                          32768L * 576, 1024L * 576, 32768L * 1024);
    // 9. softmax
    softmax_kernel<<<65536, 256>>>(sc, mask);
    // 10. oc[b] = probs @ kv_n[b]  (z = b)
    sgemm<false><<<dim3(4, 256, 2), blk>>>(sc, kf, oc, 32768, 512, 1024,
                                           1024, 576, 512,
                                           32768L * 1024, 1024L * 576, 32768L * 512);
    // 11. v proj: ov[s, h*128+d] = oc[(s,h),:] @ wkv_b[h,128:,:]^T  (z = h)
    sgemm<true><<<dim3(1, 16, 32), blk>>>(oc, wkv_b + 128 * 512, ov, 2048, 128, 512,
                                          32 * 512, 512, 4096,
                                          512, 256L * 512, 128);
    // 12. out = ov @ wo
    sgemm<false><<<dim3(32, 16, 1), blk>>>(ov, wo, out, 2048, 4096, 4096,
                                           4096, 4096, 4096, 0, 0, 0);
}

// round 6
// speedup vs baseline: 3.3226x; 3.3226x over previous
#include <cuda_runtime.h>
#include <cuda_bf16.h>
#include <cstdint>
#include <math.h>

// ---------------------------------------------------------------------------
// MLA forward. GEMMs on tensor pipe via mma.sync m16n8k8 tf32 (fp32 I/O).
// Pipeline:
//  1. qa = x @ wq_a
//  2. qa = rmsnorm(qa)*q_norm_w
//  3. q  = qa @ wq_b
//  4. kv = x @ wkv_a
//  5. kf = [rmsnorm(kv[:,:512]) | rope(kv[:,512:])]
//  6. qf[:,512:576] = rope(q_pe)
//  7. qf[:,0:512]   = q_nope @ wkv_b[h,:128,:]      (z=h)
//  8. sc[b] = qf[b] @ kf[b]^T                        (z=b, TB)
//  9. softmax(sc*SCALE + mask)
// 10. oc[b] = sc[b] @ kf[b][:,0:512]                 (z=b)
// 11. ov = oc @ wkv_b[h,128:,:]^T                    (z=h, TB)
// 12. out = ov @ wo
// ---------------------------------------------------------------------------

static constexpr int BM = 128, BN = 128, BK = 16, PAD = 4;

// scratch
__device__ __align__(256) float g_qa[2048L * 1536];
__device__ __align__(256) float g_q [2048L * 6144];
__device__ __align__(256) float g_kv[2048L * 576];
__device__ __align__(256) float g_kf[2048L * 576];
__device__ __align__(256) float g_qf[2048L * 32 * 576];
__device__ __align__(256) float g_sc[2L * 32768 * 1024];
__device__ __align__(256) float g_oc[2048L * 32 * 512];
__device__ __align__(256) float g_ov[2048L * 4096];

__device__ __forceinline__ uint32_t f2tf(float f) {
    uint32_t u;
    asm("cvt.rna.tf32.f32 %0, %1;" : "=r"(u) : "f"(f));
    return u;
}

__device__ __forceinline__ void cpa16(uint32_t smem, const float* g, bool pred) {
    int sz = pred ? 16 : 0;
    asm volatile("cp.async.cg.shared.global [%0], [%1], 16, %2;\n"
                 :: "r"(smem), "l"(g), "r"(sz));
}
__device__ __forceinline__ void cpa_commit() { asm volatile("cp.async.commit_group;\n"); }
template <int N> __device__ __forceinline__ void cpa_wait() {
    asm volatile("cp.async.wait_group %0;\n" :: "n"(N));
}

__device__ __forceinline__ void mma_tf32(float c[4], uint32_t a0, uint32_t a1,
                                         uint32_t a2, uint32_t a3,
                                         uint32_t b0, uint32_t b1) {
    asm volatile(
        "mma.sync.aligned.m16n8k8.row.col.f32.tf32.tf32.f32 "
        "{%0,%1,%2,%3},{%4,%5,%6,%7},{%8,%9},{%0,%1,%2,%3};\n"
        : "+f"(c[0]), "+f"(c[1]), "+f"(c[2]), "+f"(c[3])
        : "r"(a0), "r"(a1), "r"(a2), "r"(a3), "r"(b0), "r"(b1));
}

// ---------------------------------------------------------------------------
// C = A @ B (or A @ B^T if TB). A: MxK row-major. !TB: B KxN. TB: B NxK.
// Tiles 128x128x16, 256 threads (2x4 warps, 64x32 each). Requirements:
// M%128==0, K%16==0, N%4==0, lda/ldb/ldc%4==0, sA/sB/sC%4==0.
// ---------------------------------------------------------------------------
template <bool TB>
__global__ __launch_bounds__(256, 2) void gemm_tc(
    const float* __restrict__ A, const float* __restrict__ B,
    float* __restrict__ C, int M, int N, int K,
    int lda, int ldb, int ldc, long sA, long sB, long sC)
{
    constexpr int BROWS = TB ? BN : BK;
    constexpr int BCOLS = TB ? (BK + PAD) : (BN + PAD);
    __shared__ __align__(16) float As[2][BM][BK + PAD];
    __shared__ __align__(16) float Bs[2][BROWS][BCOLS];

    A += (long)blockIdx.z * sA;
    B += (long)blockIdx.z * sB;
    C += (long)blockIdx.z * sC;
    const int n0 = blockIdx.x * BN;
    const int m0 = blockIdx.y * BM;
    const int tid = threadIdx.x;
    const int warp = tid >> 5, lane = tid & 31;
    const int wm = warp & 1, wn = warp >> 1;      // 2 x 4 warp grid
    const int m0w = wm * 64, n0w = wn * 32;
    const int g = lane >> 2, t = lane & 3;

    float acc[4][4][4];
#pragma unroll
    for (int i = 0; i < 4; i++)
#pragma unroll
        for (int j = 0; j < 4; j++)
#pragma unroll
            for (int r = 0; r < 4; r++) acc[i][j][r] = 0.f;

    const int KT = K / BK;

    auto load_stage = [&](int st, int k0) {
        // A tile: 128 rows x 16 cols = 512 16B chunks
#pragma unroll
        for (int c = tid; c < 512; c += 256) {
            int row = c >> 2, kc = (c & 3) * 4;
            uint32_t d = (uint32_t)__cvta_generic_to_shared(&As[st][row][kc]);
            cpa16(d, A + (long)(m0 + row) * lda + k0 + kc, true);
        }
        if (!TB) {
            // B tile: 16 rows x 128 cols
#pragma unroll
            for (int c = tid; c < 512; c += 256) {
                int row = c >> 5, col = (c & 31) * 4;
                bool v = (n0 + col) < N;
                uint32_t d = (uint32_t)__cvta_generic_to_shared(&Bs[st][row][col]);
                cpa16(d, B + (long)(k0 + row) * ldb + n0 + col, v);
            }
        } else {
            // B tile: 128 n-rows x 16 k-cols
#pragma unroll
            for (int c = tid; c < 512; c += 256) {
                int row = c >> 2, kc = (c & 3) * 4;
                bool v = (n0 + row) < N;
                uint32_t d = (uint32_t)__cvta_generic_to_shared(&Bs[st][row][kc]);
                cpa16(d, B + (long)(n0 + row) * ldb + k0 + kc, v);
            }
        }
        cpa_commit();
    };

    load_stage(0, 0);

    for (int kt = 0; kt < KT; ++kt) {
        const int st = kt & 1;
        if (kt + 1 < KT) {
            load_stage(st ^ 1, (kt + 1) * BK);
            cpa_wait<1>();
        } else {
            cpa_wait<0>();
        }
        __syncthreads();

#pragma unroll
        for (int ks = 0; ks < 2; ks++) {
            const int kk = ks * 8;
            uint32_t af[4][4], bf[4][2];
#pragma unroll
            for (int mt = 0; mt < 4; mt++) {
                const int mr = m0w + mt * 16;
                af[mt][0] = f2tf(As[st][mr + g][kk + t]);
                af[mt][1] = f2tf(As[st][mr + g + 8][kk + t]);
                af[mt][2] = f2tf(As[st][mr + g][kk + t + 4]);
                af[mt][3] = f2tf(As[st][mr + g + 8][kk + t + 4]);
            }
#pragma unroll
            for (int nt = 0; nt < 4; nt++) {
                const int nc = n0w + nt * 8 + g;
                if (!TB) {
                    bf[nt][0] = f2tf(Bs[st][kk + t][nc]);
                    bf[nt][1] = f2tf(Bs[st][kk + t + 4][nc]);
                } else {
                    bf[nt][0] = f2tf(Bs[st][nc][kk + t]);
                    bf[nt][1] = f2tf(Bs[st][nc][kk + t + 4]);
                }
            }
#pragma unroll
            for (int mt = 0; mt < 4; mt++)
#pragma unroll
                for (int nt = 0; nt < 4; nt++)
                    mma_tf32(acc[mt][nt], af[mt][0], af[mt][1], af[mt][2], af[mt][3],
                             bf[nt][0], bf[nt][1]);
        }
        __syncthreads();
    }

    // epilogue
#pragma unroll
    for (int mt = 0; mt < 4; mt++) {
        const int mr = m0 + m0w + mt * 16 + g;
        float* Cp0 = C + (long)mr * ldc;
        float* Cp1 = C + (long)(mr + 8) * ldc;
#pragma unroll
        for (int nt = 0; nt < 4; nt++) {
            int gn = n0 + n0w + nt * 8 + t * 2;
            if (gn < N) {
                *reinterpret_cast<float2*>(Cp0 + gn) = make_float2(acc[mt][nt][0], acc[mt][nt][1]);
                *reinterpret_cast<float2*>(Cp1 + gn) = make_float2(acc[mt][nt][2], acc[mt][nt][3]);
            }
        }
    }
}

// ---------------------------------------------------------------------------
template <bool IS_MAX>
__device__ __forceinline__ float block_reduce(float v, float* sh)
{
    __syncthreads();
#pragma unroll
    for (int o = 16; o; o >>= 1) {
        float t = __shfl_xor_sync(0xffffffffu, v, o);
        v = IS_MAX ? fmaxf(v, t) : v + t;
    }
    const int lane = threadIdx.x & 31, w = threadIdx.x >> 5;
    if (lane == 0) sh[w] = v;
    __syncthreads();
    const int nw = blockDim.x >> 5;
    if (w == 0) {
        v = (lane < nw) ? sh[lane] : (IS_MAX ? -INFINITY : 0.f);
#pragma unroll
        for (int o = 16; o; o >>= 1) {
            float t = __shfl_xor_sync(0xffffffffu, v, o);
            v = IS_MAX ? fmaxf(v, t) : v + t;
        }
        if (lane == 0) sh[0] = v;
    }
    __syncthreads();
    return sh[0];
}

__global__ void rmsnorm_kernel(const float* __restrict__ in, const float* __restrict__ w,
                               float* __restrict__ out, int width, int ldin, int ldout)
{
    __shared__ float sh[32];
    const long row = blockIdx.x;
    const float* x = in + row * ldin;
    float* y = out + row * ldout;
    float ss = 0.f;
    for (int i = threadIdx.x; i < width; i += blockDim.x) {
        float v = x[i];
        ss += v * v;
    }
    float tot = block_reduce<false>(ss, sh);
    float rinv = rsqrtf(tot / (float)width + 1e-6f);
    for (int i = threadIdx.x; i < width; i += blockDim.x)
        y[i] = x[i] * rinv * w[i];
}

__global__ void rope_k(const float* __restrict__ kv, const float* __restrict__ fc,
                       float* __restrict__ kf)
{
    int idx = blockIdx.x * blockDim.x + threadIdx.x;
    int t = idx >> 5, i = idx & 31;
    int pos = t & 1023;
    float c = fc[(pos * 32 + i) * 2 + 0];
    float s = fc[(pos * 32 + i) * 2 + 1];
    float xe = kv[(long)t * 576 + 512 + 2 * i];
    float xo = kv[(long)t * 576 + 513 + 2 * i];
    kf[(long)t * 576 + 512 + 2 * i] = xe * c - xo * s;
    kf[(long)t * 576 + 513 + 2 * i] = xe * s + xo * c;
}

__global__ void rope_q(const float* __restrict__ q, const float* __restrict__ fc,
                       float* __restrict__ qf)
{
    long idx = (long)blockIdx.x * blockDim.x + threadIdx.x;
    int i = idx & 31;
    int h = (idx >> 5) & 31;
    long r = idx >> 10;
    int pos = (int)(r & 1023);
    const float* src = q + r * 6144 + h * 192 + 128 + 2 * i;
    float xe = src[0], xo = src[1];
    float c = fc[(pos * 32 + i) * 2 + 0];
    float s = fc[(pos * 32 + i) * 2 + 1];
    float* dst = qf + (r * 32 + h) * 576 + 512 + 2 * i;
    dst[0] = xe * c - xo * s;
    dst[1] = xe * s + xo * c;
}

__global__ __launch_bounds__(256) void softmax_kernel(float* __restrict__ sc,
                                                      const float* __restrict__ mask)
{
    __shared__ float sh[32];
    const long m = blockIdx.x;
    const int srow = (int)((m & 32767) >> 5);
    float* p = sc + m * 1024;
    const float* mk = mask + (long)srow * 1024;
    const float scale = 0.07216878364870322f;
    const int tid = threadIdx.x;
    float l[4];
    float mx = -INFINITY;
#pragma unroll
    for (int j = 0; j < 4; j++) {
        int t = tid + j * 256;
        l[j] = p[t] * scale + mk[t];
        mx = fmaxf(mx, l[j]);
    }
    float M = block_reduce<true>(mx, sh);
    float s = 0.f;
#pragma unroll
    for (int j = 0; j < 4; j++) {
        l[j] = expf(l[j] - M);
        s += l[j];
    }
    float S = block_reduce<false>(s, sh);
    float inv = 1.f / S;
#pragma unroll
    for (int j = 0; j < 4; j++) p[tid + j * 256] = l[j] * inv;
}

// ---------------------------------------------------------------------------
extern "C" void kernel_launch(void* const* d_in, const int* in_sizes, int n_in,
                              void* d_out, int out_size)
{
    const float* x        = (const float*)d_in[0];
    const float* fc       = (const float*)d_in[1];
    const float* mask     = (const float*)d_in[2];
    const float* wq_a     = (const float*)d_in[3];
    const float* q_norm_w = (const float*)d_in[4];
    const float* wq_b     = (const float*)d_in[5];
    const float* wkv_a    = (const float*)d_in[6];
    const float* kv_norm_w= (const float*)d_in[7];
    const float* wkv_b    = (const float*)d_in[8];
    const float* wo       = (const float*)d_in[9];
    float* out = (float*)d_out;

    float *qa, *q, *kv, *kf, *qf, *sc, *oc, *ov;
    cudaGetSymbolAddress((void**)&qa, g_qa);
    cudaGetSymbolAddress((void**)&q,  g_q);
    cudaGetSymbolAddress((void**)&kv, g_kv);
    cudaGetSymbolAddress((void**)&kf, g_kf);
    cudaGetSymbolAddress((void**)&qf, g_qf);
    cudaGetSymbolAddress((void**)&sc, g_sc);
    cudaGetSymbolAddress((void**)&oc, g_oc);
    cudaGetSymbolAddress((void**)&ov, g_ov);

    const dim3 blk(256);

    // 1. qa = x @ wq_a
    gemm_tc<false><<<dim3(12, 16, 1), blk>>>(x, wq_a, qa, 2048, 1536, 4096,
                                             4096, 1536, 1536, 0, 0, 0);
    // 2. rmsnorm qa
    rmsnorm_kernel<<<2048, 256>>>(qa, q_norm_w, qa, 1536, 1536, 1536);
    // 3. q = qa @ wq_b
    gemm_tc<false><<<dim3(48, 16, 1), blk>>>(qa, wq_b, q, 2048, 6144, 1536,
                                             1536, 6144, 6144, 0, 0, 0);
    // 4. kv = x @ wkv_a
    gemm_tc<false><<<dim3(5, 16, 1), blk>>>(x, wkv_a, kv, 2048, 576, 4096,
                                            4096, 576, 576, 0, 0, 0);
    // 5. k_full
    rmsnorm_kernel<<<2048, 256>>>(kv, kv_norm_w, kf, 512, 576, 576);
    rope_k<<<256, 256>>>(kv, fc, kf);
    // 6. q_pe rope
    rope_q<<<2048, 1024>>>(q, fc, qf);
    // 7. q absorb (z = h)
    gemm_tc<false><<<dim3(4, 16, 32), blk>>>(q, wkv_b, qf, 2048, 512, 128,
                                             6144, 512, 32 * 576,
                                             192, 256L * 512, 576);
    // 8. scores (z = b, TB)
    gemm_tc<true><<<dim3(8, 256, 2), blk>>>(qf, kf, sc, 32768, 1024, 576,
                                            576, 576, 1024,
                                            32768L * 576, 1024L * 576, 32768L * 1024);
    // 9. softmax
    softmax_kernel<<<65536, 256>>>(sc, mask);
    // 10. PV (z = b)
    gemm_tc<false><<<dim3(4, 256, 2), blk>>>(sc, kf, oc, 32768, 512, 1024,
                                             1024, 576, 512,
                                             32768L * 1024, 1024L * 576, 32768L * 512);
    // 11. v proj (z = h, TB)
    gemm_tc<true><<<dim3(1, 16, 32), blk>>>(oc, wkv_b + 128 * 512, ov, 2048, 128, 512,
                                            32 * 512, 512, 4096,
                                            512, 256L * 512, 128);
    // 12. out = ov @ wo
    gemm_tc<false><<<dim3(32, 16, 1), blk>>>(ov, wo, out, 2048, 4096, 4096,
                                             4096, 4096, 4096, 0, 0, 0);
}

// round 8
// speedup vs baseline: 3.7209x; 1.1199x over previous
#include <cuda_runtime.h>
#include <cuda_bf16.h>
#include <cstdint>
#include <math.h>

// ---------------------------------------------------------------------------
// MLA forward. tf32 mma.sync GEMMs, 4-stage cp.async pipeline, causal skipping.
//  1. qa = x @ wq_a
//  2. qa = rmsnorm(qa)*q_norm_w
//  3. q  = qa @ wq_b
//  4. kv = x @ wkv_a
//  5. kf = [rmsnorm(kv[:,:512]) | rope(kv[:,512:])]
//  6. qf[:,512:576] = rope(q_pe)
//  7. qf[:,0:512]   = q_nope @ wkv_b[h,:128,:]      (z=h)
//  8. sc[b] = qf[b] @ kf[b]^T   -- causal: skip fully-masked key tiles
//  9. softmax(sc*SCALE + mask)  -- width limited to W(row block)
// 10. oc[b] = sc[b] @ kf[b][:,0:512]  -- K limited to W(row block)
// 11. ov = oc @ wkv_b[h,128:,:]^T                   (z=h, TB)
// 12. out = ov @ wo
// ---------------------------------------------------------------------------

static constexpr int BM = 128, BN = 128, BK = 16, PAD = 4, STAGES = 4;

// scratch
__device__ __align__(256) float g_qa[2048L * 1536];
__device__ __align__(256) float g_q [2048L * 6144];
__device__ __align__(256) float g_kv[2048L * 576];
__device__ __align__(256) float g_kf[2048L * 576];
__device__ __align__(256) float g_qf[2048L * 32 * 576];
__device__ __align__(256) float g_sc[2L * 32768 * 1024];
__device__ __align__(256) float g_oc[2048L * 32 * 512];
__device__ __align__(256) float g_ov[2048L * 4096];

__device__ __forceinline__ uint32_t f2tf(float f) {
    uint32_t u;
    asm("cvt.rna.tf32.f32 %0, %1;" : "=r"(u) : "f"(f));
    return u;
}

__device__ __forceinline__ void cpa16(uint32_t smem, const float* g, bool pred) {
    int sz = pred ? 16 : 0;
    asm volatile("cp.async.cg.shared.global [%0], [%1], 16, %2;\n"
                 :: "r"(smem), "l"(g), "r"(sz));
}
__device__ __forceinline__ void cpa_commit() { asm volatile("cp.async.commit_group;\n"); }
template <int N> __device__ __forceinline__ void cpa_wait() {
    asm volatile("cp.async.wait_group %0;\n" :: "n"(N));
}

__device__ __forceinline__ void mma_tf32(float c[4], uint32_t a0, uint32_t a1,
                                         uint32_t a2, uint32_t a3,
                                         uint32_t b0, uint32_t b1) {
    asm volatile(
        "mma.sync.aligned.m16n8k8.row.col.f32.tf32.tf32.f32 "
        "{%0,%1,%2,%3},{%4,%5,%6,%7},{%8,%9},{%0,%1,%2,%3};\n"
        : "+f"(c[0]), "+f"(c[1]), "+f"(c[2]), "+f"(c[3])
        : "r"(a0), "r"(a1), "r"(a2), "r"(a3), "r"(b0), "r"(b1));
}

// ---------------------------------------------------------------------------
// C = A @ B (or A @ B^T if TB). A: MxK row-major. !TB: B KxN. TB: B NxK.
// 128x128x16 tiles, 256 threads (2x4 warps, 64x32 each), 4-stage cp.async.
// CN: skip whole CTA when n0 beyond causal width W(m0) (scores).
// CK: clamp K to W(m0) (PV).  W = round16(m0/32 + 4); rows are (s*32+h).
// Requirements: M%128==0, K%16==0 (and W%16==0), N%4, lds %4.
// ---------------------------------------------------------------------------
template <bool TB, bool CN, bool CK>
__global__ __launch_bounds__(256, 2) void gemm_tc(
    const float* __restrict__ A, const float* __restrict__ B,
    float* __restrict__ C, int M, int N, int K,
    int lda, int ldb, int ldc, long sA, long sB, long sC)
{
    constexpr int BROWS = TB ? BN : BK;
    constexpr int BCOLS = TB ? (BK + PAD) : (BN + PAD);
    extern __shared__ __align__(16) float dyn[];
    float (*As)[BM][BK + PAD] = reinterpret_cast<float(*)[BM][BK + PAD]>(dyn);
    float (*Bs)[BROWS][BCOLS] =
        reinterpret_cast<float(*)[BROWS][BCOLS]>(dyn + STAGES * BM * (BK + PAD));

    const int n0 = blockIdx.x * BN;
    const int m0 = blockIdx.y * BM;
    const int W  = ((m0 >> 5) + 19) & ~15;   // causal width for this row block
    if (CN && n0 >= W) return;
    const int Keff = CK ? (W < K ? W : K) : K;

    A += (long)blockIdx.z * sA;
    B += (long)blockIdx.z * sB;
    C += (long)blockIdx.z * sC;
    const int tid = threadIdx.x;
    const int warp = tid >> 5, lane = tid & 31;
    const int wm = warp & 1, wn = warp >> 1;      // 2 x 4 warp grid
    const int m0w = wm * 64, n0w = wn * 32;
    const int g = lane >> 2, t = lane & 3;

    float acc[4][4][4];
#pragma unroll
    for (int i = 0; i < 4; i++)
#pragma unroll
        for (int j = 0; j < 4; j++)
#pragma unroll
            for (int r = 0; r < 4; r++) acc[i][j][r] = 0.f;

    const int KT = Keff / BK;

    auto load_stage = [&](int st, int k0) {
        // A tile: 128 rows x 16 cols = 512 16B chunks
#pragma unroll
        for (int c = tid; c < 512; c += 256) {
            int row = c >> 2, kc = (c & 3) * 4;
            uint32_t d = (uint32_t)__cvta_generic_to_shared(&As[st][row][kc]);
            cpa16(d, A + (long)(m0 + row) * lda + k0 + kc, true);
        }
        if (!TB) {
#pragma unroll
            for (int c = tid; c < 512; c += 256) {
                int row = c >> 5, col = (c & 31) * 4;
                bool v = (n0 + col) < N;
                uint32_t d = (uint32_t)__cvta_generic_to_shared(&Bs[st][row][col]);
                cpa16(d, B + (long)(k0 + row) * ldb + n0 + col, v);
            }
        } else {
#pragma unroll
            for (int c = tid; c < 512; c += 256) {
                int row = c >> 2, kc = (c & 3) * 4;
                bool v = (n0 + row) < N;
                uint32_t d = (uint32_t)__cvta_generic_to_shared(&Bs[st][row][kc]);
                cpa16(d, B + (long)(n0 + row) * ldb + k0 + kc, v);
            }
        }
        cpa_commit();
    };

    // prologue: keep exactly 3 groups outstanding (empty-commit padding)
    load_stage(0, 0);
    if (KT > 1) load_stage(1, BK); else cpa_commit();
    if (KT > 2) load_stage(2, 2 * BK); else cpa_commit();

    for (int kt = 0; kt < KT; ++kt) {
        cpa_wait<2>();          // group kt complete
        __syncthreads();        // everyone done with buffer (kt-1)&3 compute
        if (kt + 3 < KT) load_stage((kt + 3) & 3, (kt + 3) * BK);
        else cpa_commit();
        const int st = kt & 3;

#pragma unroll
        for (int ks = 0; ks < 2; ks++) {
            const int kk = ks * 8;
            uint32_t af[4][4], bf[4][2];
#pragma unroll
            for (int mt = 0; mt < 4; mt++) {
                const int mr = m0w + mt * 16;
                af[mt][0] = f2tf(As[st][mr + g][kk + t]);
                af[mt][1] = f2tf(As[st][mr + g + 8][kk + t]);
                af[mt][2] = f2tf(As[st][mr + g][kk + t + 4]);
                af[mt][3] = f2tf(As[st][mr + g + 8][kk + t + 4]);
            }
#pragma unroll
            for (int nt = 0; nt < 4; nt++) {
                const int nc = n0w + nt * 8 + g;
                if (!TB) {
                    bf[nt][0] = f2tf(Bs[st][kk + t][nc]);
                    bf[nt][1] = f2tf(Bs[st][kk + t + 4][nc]);
                } else {
                    bf[nt][0] = f2tf(Bs[st][nc][kk + t]);
                    bf[nt][1] = f2tf(Bs[st][nc][kk + t + 4]);
                }
            }
#pragma unroll
            for (int mt = 0; mt < 4; mt++)
#pragma unroll
                for (int nt = 0; nt < 4; nt++)
                    mma_tf32(acc[mt][nt], af[mt][0], af[mt][1], af[mt][2], af[mt][3],
                             bf[nt][0], bf[nt][1]);
        }
    }

    // epilogue
#pragma unroll
    for (int mt = 0; mt < 4; mt++) {
        const int mr = m0 + m0w + mt * 16 + g;
        float* Cp0 = C + (long)mr * ldc;
        float* Cp1 = C + (long)(mr + 8) * ldc;
#pragma unroll
        for (int nt = 0; nt < 4; nt++) {
            int gn = n0 + n0w + nt * 8 + t * 2;
            if (gn < N) {
                *reinterpret_cast<float2*>(Cp0 + gn) = make_float2(acc[mt][nt][0], acc[mt][nt][1]);
                *reinterpret_cast<float2*>(Cp1 + gn) = make_float2(acc[mt][nt][2], acc[mt][nt][3]);
            }
        }
    }
}

// ---------------------------------------------------------------------------
template <bool IS_MAX>
__device__ __forceinline__ float block_reduce(float v, float* sh)
{
    __syncthreads();
#pragma unroll
    for (int o = 16; o; o >>= 1) {
        float t = __shfl_xor_sync(0xffffffffu, v, o);
        v = IS_MAX ? fmaxf(v, t) : v + t;
    }
    const int lane = threadIdx.x & 31, w = threadIdx.x >> 5;
    if (lane == 0) sh[w] = v;
    __syncthreads();
    const int nw = blockDim.x >> 5;
    if (w == 0) {
        v = (lane < nw) ? sh[lane] : (IS_MAX ? -INFINITY : 0.f);
#pragma unroll
        for (int o = 16; o; o >>= 1) {
            float t = __shfl_xor_sync(0xffffffffu, v, o);
            v = IS_MAX ? fmaxf(v, t) : v + t;
        }
        if (lane == 0) sh[0] = v;
    }
    __syncthreads();
    return sh[0];
}

__global__ void rmsnorm_kernel(const float* __restrict__ in, const float* __restrict__ w,
                               float* __restrict__ out, int width, int ldin, int ldout)
{
    __shared__ float sh[32];
    const long row = blockIdx.x;
    const float* x = in + row * ldin;
    float* y = out + row * ldout;
    float ss = 0.f;
    for (int i = threadIdx.x; i < width; i += blockDim.x) {
        float v = x[i];
        ss += v * v;
    }
    float tot = block_reduce<false>(ss, sh);
    float rinv = rsqrtf(tot / (float)width + 1e-6f);
    for (int i = threadIdx.x; i < width; i += blockDim.x)
        y[i] = x[i] * rinv * w[i];
}

__global__ void rope_k(const float* __restrict__ kv, const float* __restrict__ fc,
                       float* __restrict__ kf)
{
    int idx = blockIdx.x * blockDim.x + threadIdx.x;
    int t = idx >> 5, i = idx & 31;
    int pos = t & 1023;
    float c = fc[(pos * 32 + i) * 2 + 0];
    float s = fc[(pos * 32 + i) * 2 + 1];
    float xe = kv[(long)t * 576 + 512 + 2 * i];
    float xo = kv[(long)t * 576 + 513 + 2 * i];
    kf[(long)t * 576 + 512 + 2 * i] = xe * c - xo * s;
    kf[(long)t * 576 + 513 + 2 * i] = xe * s + xo * c;
}

__global__ void rope_q(const float* __restrict__ q, const float* __restrict__ fc,
                       float* __restrict__ qf)
{
    long idx = (long)blockIdx.x * blockDim.x + threadIdx.x;
    int i = idx & 31;
    int h = (idx >> 5) & 31;
    long r = idx >> 10;
    int pos = (int)(r & 1023);
    const float* src = q + r * 6144 + h * 192 + 128 + 2 * i;
    float xe = src[0], xo = src[1];
    float c = fc[(pos * 32 + i) * 2 + 0];
    float s = fc[(pos * 32 + i) * 2 + 1];
    float* dst = qf + (r * 32 + h) * 576 + 512 + 2 * i;
    dst[0] = xe * c - xo * s;
    dst[1] = xe * s + xo * c;
}

// softmax over causal width W of one row; masked tail inside W written as 0.
__global__ __launch_bounds__(256) void softmax_kernel(float* __restrict__ sc,
                                                      const float* __restrict__ mask)
{
    __shared__ float sh[32];
    const long m = blockIdx.x;
    const int srow = (int)((m & 32767) >> 5);         // query position s
    const int W = ((srow & ~3) + 19) & ~15;           // block causal width
    float* p = sc + m * 1024;
    const float* mk = mask + (long)srow * 1024;
    const float scale = 0.07216878364870322f;
    const int tid = threadIdx.x;
    float l[4];
    float mx = -INFINITY;
#pragma unroll
    for (int j = 0; j < 4; j++) {
        int t = tid + j * 256;
        if (t < W) {
            l[j] = p[t] * scale + mk[t];
            mx = fmaxf(mx, l[j]);
        } else l[j] = -INFINITY;
    }
    float M = block_reduce<true>(mx, sh);
    float s = 0.f;
#pragma unroll
    for (int j = 0; j < 4; j++) {
        int t = tid + j * 256;
        if (t < W) {
            l[j] = expf(l[j] - M);
            s += l[j];
        }
    }
    float S = block_reduce<false>(s, sh);
    float inv = 1.f / S;
#pragma unroll
    for (int j = 0; j < 4; j++) {
        int t = tid + j * 256;
        if (t < W) p[t] = l[j] * inv;
    }
}

// ---------------------------------------------------------------------------
extern "C" void kernel_launch(void* const* d_in, const int* in_sizes, int n_in,
                              void* d_out, int out_size)
{
    const float* x        = (const float*)d_in[0];
    const float* fc       = (const float*)d_in[1];
    const float* mask     = (const float*)d_in[2];
    const float* wq_a     = (const float*)d_in[3];
    const float* q_norm_w = (const float*)d_in[4];
    const float* wq_b     = (const float*)d_in[5];
    const float* wkv_a    = (const float*)d_in[6];
    const float* kv_norm_w= (const float*)d_in[7];
    const float* wkv_b    = (const float*)d_in[8];
    const float* wo       = (const float*)d_in[9];
    float* out = (float*)d_out;

    float *qa, *q, *kv, *kf, *qf, *sc, *oc, *ov;
    cudaGetSymbolAddress((void**)&qa, g_qa);
    cudaGetSymbolAddress((void**)&q,  g_q);
    cudaGetSymbolAddress((void**)&kv, g_kv);
    cudaGetSymbolAddress((void**)&kf, g_kf);
    cudaGetSymbolAddress((void**)&qf, g_qf);
    cudaGetSymbolAddress((void**)&sc, g_sc);
    cudaGetSymbolAddress((void**)&oc, g_oc);
    cudaGetSymbolAddress((void**)&ov, g_ov);

    // dynamic smem sizes
    const int SM_NT = STAGES * (BM * (BK + PAD) + BK * (BN + PAD)) * 4;   // 74752
    const int SM_TB = STAGES * (BM * (BK + PAD) + BN * (BK + PAD)) * 4;   // 81920
    cudaFuncSetAttribute(gemm_tc<false, false, false>,
                         cudaFuncAttributeMaxDynamicSharedMemorySize, SM_NT);
    cudaFuncSetAttribute(gemm_tc<true, false, false>,
                         cudaFuncAttributeMaxDynamicSharedMemorySize, SM_TB);
    cudaFuncSetAttribute(gemm_tc<true, true, false>,
                         cudaFuncAttributeMaxDynamicSharedMemorySize, SM_TB);
    cudaFuncSetAttribute(gemm_tc<false, false, true>,
                         cudaFuncAttributeMaxDynamicSharedMemorySize, SM_NT);

    const dim3 blk(256);

    // 1. qa = x @ wq_a
    gemm_tc<false, false, false><<<dim3(12, 16, 1), blk, SM_NT>>>(
        x, wq_a, qa, 2048, 1536, 4096, 4096, 1536, 1536, 0, 0, 0);
    // 2. rmsnorm qa
    rmsnorm_kernel<<<2048, 256>>>(qa, q_norm_w, qa, 1536, 1536, 1536);
    // 3. q = qa @ wq_b
    gemm_tc<false, false, false><<<dim3(48, 16, 1), blk, SM_NT>>>(
        qa, wq_b, q, 2048, 6144, 1536, 1536, 6144, 6144, 0, 0, 0);
    // 4. kv = x @ wkv_a
    gemm_tc<false, false, false><<<dim3(5, 16, 1), blk, SM_NT>>>(
        x, wkv_a, kv, 2048, 576, 4096, 4096, 576, 576, 0, 0, 0);
    // 5. k_full
    rmsnorm_kernel<<<2048, 256>>>(kv, kv_norm_w, kf, 512, 576, 576);
    rope_k<<<256, 256>>>(kv, fc, kf);
    // 6. q_pe rope
    rope_q<<<2048, 1024>>>(q, fc, qf);
    // 7. q absorb (z = h)
    gemm_tc<false, false, false><<<dim3(4, 16, 32), blk, SM_NT>>>(
        q, wkv_b, qf, 2048, 512, 128, 6144, 512, 32 * 576,
        192, 256L * 512, 576);
    // 8. scores (z = b, TB, causal skip)
    gemm_tc<true, true, false><<<dim3(8, 256, 2), blk, SM_TB>>>(
        qf, kf, sc, 32768, 1024, 576, 576, 576, 1024,
        32768L * 576, 1024L * 576, 32768L * 1024);
    // 9. softmax (causal width)
    softmax_kernel<<<65536, 256>>>(sc, mask);
    // 10. PV (z = b, causal K clamp)
    gemm_tc<false, false, true><<<dim3(4, 256, 2), blk, SM_NT>>>(
        sc, kf, oc, 32768, 512, 1024, 1024, 576, 512,
        32768L * 1024, 1024L * 576, 32768L * 512);
    // 11. v proj (z = h, TB)
    gemm_tc<true, false, false><<<dim3(1, 16, 32), blk, SM_TB>>>(
        oc, wkv_b + 128 * 512, ov, 2048, 128, 512, 32 * 512, 512, 4096,
        512, 256L * 512, 128);
    // 12. out = ov @ wo
    gemm_tc<false, false, false><<<dim3(32, 16, 1), blk, SM_NT>>>(
        ov, wo, out, 2048, 4096, 4096, 4096, 4096, 4096, 0, 0, 0);
}

// round 9
// speedup vs baseline: 3.8403x; 1.0321x over previous
#include <cuda_runtime.h>
#include <cuda_bf16.h>
#include <cstdint>
#include <math.h>

// ---------------------------------------------------------------------------
// MLA forward. tf32 mma.sync GEMMs; all GEMM inputs pre-rounded to tf32 at
// their producers so the GEMM inner loop is pure LDS + MMA (no cvt).
//  0. round x + all weights to tf32 (scratch copies)
//  1. qa = x @ wq_a                       (no round: feeds rmsnorm)
//  2. qa = rmsnorm(qa)*q_norm_w           (rounded write)
//  3. q  = qa @ wq_b                      (rounded write)
//  4. kv = x @ wkv_a                      (no round: feeds rmsnorm/rope)
//  5. kf = [rmsnorm(kv[:,:512]) | rope(kv[:,512:])]   (rounded)
//  6. qf[:,512:576] = rope(q_pe)          (rounded)
//  7. qf[:,0:512]   = q_nope @ wkv_b[h,:128,:]  (rounded, z=h)
//  8. sc[b] = qf[b] @ kf[b]^T   (causal skip; no round: feeds softmax)
//  9. softmax(sc*SCALE + mask)            (rounded write)
// 10. oc[b] = sc[b] @ kf[b][:,0:512]      (rounded, causal K clamp)
// 11. ov = oc @ wkv_b[h,128:,:]^T         (rounded, z=h, TB)
// 12. out = ov @ wo                       (NOT rounded: final output)
// ---------------------------------------------------------------------------

static constexpr int BM = 128, BN = 128, BK = 16, PAD = 4, STAGES = 4;

// scratch
__device__ __align__(256) float g_qa[2048L * 1536];
__device__ __align__(256) float g_q [2048L * 6144];
__device__ __align__(256) float g_kv[2048L * 576];
__device__ __align__(256) float g_kf[2048L * 576];
__device__ __align__(256) float g_qf[2048L * 32 * 576];
__device__ __align__(256) float g_sc[2L * 32768 * 1024];
__device__ __align__(256) float g_oc[2048L * 32 * 512];
__device__ __align__(256) float g_ov[2048L * 4096];
// tf32-rounded copies of inputs
__device__ __align__(256) float g_xr [2048L * 4096];
__device__ __align__(256) float g_w1 [4096L * 1536];   // wq_a
__device__ __align__(256) float g_w2 [1536L * 6144];   // wq_b
__device__ __align__(256) float g_w3 [4096L * 576];    // wkv_a
__device__ __align__(256) float g_w4 [32L * 256 * 512];// wkv_b
__device__ __align__(256) float g_w5 [4096L * 4096];   // wo

__device__ __forceinline__ uint32_t f2tf(float f) {
    uint32_t u;
    asm("cvt.rna.tf32.f32 %0, %1;" : "=r"(u) : "f"(f));
    return u;
}
__device__ __forceinline__ float rtf(float f) { return __uint_as_float(f2tf(f)); }

__device__ __forceinline__ void cpa16(uint32_t smem, const float* g, bool pred) {
    int sz = pred ? 16 : 0;
    asm volatile("cp.async.cg.shared.global [%0], [%1], 16, %2;\n"
                 :: "r"(smem), "l"(g), "r"(sz));
}
__device__ __forceinline__ void cpa_commit() { asm volatile("cp.async.commit_group;\n"); }
template <int N> __device__ __forceinline__ void cpa_wait() {
    asm volatile("cp.async.wait_group %0;\n" :: "n"(N));
}

__device__ __forceinline__ void mma_tf32(float c[4], uint32_t a0, uint32_t a1,
                                         uint32_t a2, uint32_t a3,
                                         uint32_t b0, uint32_t b1) {
    asm volatile(
        "mma.sync.aligned.m16n8k8.row.col.f32.tf32.tf32.f32 "
        "{%0,%1,%2,%3},{%4,%5,%6,%7},{%8,%9},{%0,%1,%2,%3};\n"
        : "+f"(c[0]), "+f"(c[1]), "+f"(c[2]), "+f"(c[3])
        : "r"(a0), "r"(a1), "r"(a2), "r"(a3), "r"(b0), "r"(b1));
}

// elementwise tf32 rounding pass (n % 4 == 0)
__global__ void round_tf32(const float* __restrict__ in, float* __restrict__ out, long n4)
{
    long i = (long)blockIdx.x * blockDim.x + threadIdx.x;
    if (i < n4) {
        float4 v = reinterpret_cast<const float4*>(in)[i];
        v.x = rtf(v.x); v.y = rtf(v.y); v.z = rtf(v.z); v.w = rtf(v.w);
        reinterpret_cast<float4*>(out)[i] = v;
    }
}

// ---------------------------------------------------------------------------
// C = A @ B (or A @ B^T if TB). Inputs assumed tf32-rounded already.
// RND: round C to tf32 on store. CN: causal CTA skip. CK: causal K clamp.
// ---------------------------------------------------------------------------
template <bool TB, bool CN, bool CK, bool RND>
__global__ __launch_bounds__(256, 2) void gemm_tc(
    const float* __restrict__ A, const float* __restrict__ B,
    float* __restrict__ C, int M, int N, int K,
    int lda, int ldb, int ldc, long sA, long sB, long sC)
{
    constexpr int BROWS = TB ? BN : BK;
    constexpr int BCOLS = TB ? (BK + PAD) : (BN + PAD);
    extern __shared__ __align__(16) float dyn[];
    float (*As)[BM][BK + PAD] = reinterpret_cast<float(*)[BM][BK + PAD]>(dyn);
    float (*Bs)[BROWS][BCOLS] =
        reinterpret_cast<float(*)[BROWS][BCOLS]>(dyn + STAGES * BM * (BK + PAD));

    const int n0 = blockIdx.x * BN;
    const int m0 = blockIdx.y * BM;
    const int W  = ((m0 >> 5) + 19) & ~15;   // causal width for this row block
    if (CN && n0 >= W) return;
    const int Keff = CK ? (W < K ? W : K) : K;

    A += (long)blockIdx.z * sA;
    B += (long)blockIdx.z * sB;
    C += (long)blockIdx.z * sC;
    const int tid = threadIdx.x;
    const int warp = tid >> 5, lane = tid & 31;
    const int wm = warp & 1, wn = warp >> 1;      // 2 x 4 warp grid
    const int m0w = wm * 64, n0w = wn * 32;
    const int g = lane >> 2, t = lane & 3;

    float acc[4][4][4];
#pragma unroll
    for (int i = 0; i < 4; i++)
#pragma unroll
        for (int j = 0; j < 4; j++)
#pragma unroll
            for (int r = 0; r < 4; r++) acc[i][j][r] = 0.f;

    const int KT = Keff / BK;

    auto load_stage = [&](int st, int k0) {
#pragma unroll
        for (int c = tid; c < 512; c += 256) {
            int row = c >> 2, kc = (c & 3) * 4;
            uint32_t d = (uint32_t)__cvta_generic_to_shared(&As[st][row][kc]);
            cpa16(d, A + (long)(m0 + row) * lda + k0 + kc, true);
        }
        if (!TB) {
#pragma unroll
            for (int c = tid; c < 512; c += 256) {
                int row = c >> 5, col = (c & 31) * 4;
                bool v = (n0 + col) < N;
                uint32_t d = (uint32_t)__cvta_generic_to_shared(&Bs[st][row][col]);
                cpa16(d, B + (long)(k0 + row) * ldb + n0 + col, v);
            }
        } else {
#pragma unroll
            for (int c = tid; c < 512; c += 256) {
                int row = c >> 2, kc = (c & 3) * 4;
                bool v = (n0 + row) < N;
                uint32_t d = (uint32_t)__cvta_generic_to_shared(&Bs[st][row][kc]);
                cpa16(d, B + (long)(n0 + row) * ldb + k0 + kc, v);
            }
        }
        cpa_commit();
    };

    load_stage(0, 0);
    if (KT > 1) load_stage(1, BK); else cpa_commit();
    if (KT > 2) load_stage(2, 2 * BK); else cpa_commit();

    for (int kt = 0; kt < KT; ++kt) {
        cpa_wait<2>();
        __syncthreads();
        if (kt + 3 < KT) load_stage((kt + 3) & 3, (kt + 3) * BK);
        else cpa_commit();
        const int st = kt & 3;

#pragma unroll
        for (int ks = 0; ks < 2; ks++) {
            const int kk = ks * 8;
            uint32_t af[4][4], bf[4][2];
#pragma unroll
            for (int mt = 0; mt < 4; mt++) {
                const int mr = m0w + mt * 16;
                af[mt][0] = __float_as_uint(As[st][mr + g][kk + t]);
                af[mt][1] = __float_as_uint(As[st][mr + g + 8][kk + t]);
                af[mt][2] = __float_as_uint(As[st][mr + g][kk + t + 4]);
                af[mt][3] = __float_as_uint(As[st][mr + g + 8][kk + t + 4]);
            }
#pragma unroll
            for (int nt = 0; nt < 4; nt++) {
                const int nc = n0w + nt * 8 + g;
                if (!TB) {
                    bf[nt][0] = __float_as_uint(Bs[st][kk + t][nc]);
                    bf[nt][1] = __float_as_uint(Bs[st][kk + t + 4][nc]);
                } else {
                    bf[nt][0] = __float_as_uint(Bs[st][nc][kk + t]);
                    bf[nt][1] = __float_as_uint(Bs[st][nc][kk + t + 4]);
                }
            }
#pragma unroll
            for (int mt = 0; mt < 4; mt++)
#pragma unroll
                for (int nt = 0; nt < 4; nt++)
                    mma_tf32(acc[mt][nt], af[mt][0], af[mt][1], af[mt][2], af[mt][3],
                             bf[nt][0], bf[nt][1]);
        }
    }

    // epilogue
#pragma unroll
    for (int mt = 0; mt < 4; mt++) {
        const int mr = m0 + m0w + mt * 16 + g;
        float* Cp0 = C + (long)mr * ldc;
        float* Cp1 = C + (long)(mr + 8) * ldc;
#pragma unroll
        for (int nt = 0; nt < 4; nt++) {
            int gn = n0 + n0w + nt * 8 + t * 2;
            if (gn < N) {
                float4 v = make_float4(acc[mt][nt][0], acc[mt][nt][1],
                                       acc[mt][nt][2], acc[mt][nt][3]);
                if (RND) { v.x = rtf(v.x); v.y = rtf(v.y); v.z = rtf(v.z); v.w = rtf(v.w); }
                *reinterpret_cast<float2*>(Cp0 + gn) = make_float2(v.x, v.y);
                *reinterpret_cast<float2*>(Cp1 + gn) = make_float2(v.z, v.w);
            }
        }
    }
}

// ---------------------------------------------------------------------------
template <bool IS_MAX>
__device__ __forceinline__ float block_reduce(float v, float* sh)
{
    __syncthreads();
#pragma unroll
    for (int o = 16; o; o >>= 1) {
        float t = __shfl_xor_sync(0xffffffffu, v, o);
        v = IS_MAX ? fmaxf(v, t) : v + t;
    }
    const int lane = threadIdx.x & 31, w = threadIdx.x >> 5;
    if (lane == 0) sh[w] = v;
    __syncthreads();
    const int nw = blockDim.x >> 5;
    if (w == 0) {
        v = (lane < nw) ? sh[lane] : (IS_MAX ? -INFINITY : 0.f);
#pragma unroll
        for (int o = 16; o; o >>= 1) {
            float t = __shfl_xor_sync(0xffffffffu, v, o);
            v = IS_MAX ? fmaxf(v, t) : v + t;
        }
        if (lane == 0) sh[0] = v;
    }
    __syncthreads();
    return sh[0];
}

// rounded-output rmsnorm
__global__ void rmsnorm_kernel(const float* __restrict__ in, const float* __restrict__ w,
                               float* __restrict__ out, int width, int ldin, int ldout)
{
    __shared__ float sh[32];
    const long row = blockIdx.x;
    const float* x = in + row * ldin;
    float* y = out + row * ldout;
    float ss = 0.f;
    for (int i = threadIdx.x; i < width; i += blockDim.x) {
        float v = x[i];
        ss += v * v;
    }
    float tot = block_reduce<false>(ss, sh);
    float rinv = rsqrtf(tot / (float)width + 1e-6f);
    for (int i = threadIdx.x; i < width; i += blockDim.x)
        y[i] = rtf(x[i] * rinv * w[i]);
}

__global__ void rope_k(const float* __restrict__ kv, const float* __restrict__ fc,
                       float* __restrict__ kf)
{
    int idx = blockIdx.x * blockDim.x + threadIdx.x;
    int t = idx >> 5, i = idx & 31;
    int pos = t & 1023;
    float c = fc[(pos * 32 + i) * 2 + 0];
    float s = fc[(pos * 32 + i) * 2 + 1];
    float xe = kv[(long)t * 576 + 512 + 2 * i];
    float xo = kv[(long)t * 576 + 513 + 2 * i];
    kf[(long)t * 576 + 512 + 2 * i] = rtf(xe * c - xo * s);
    kf[(long)t * 576 + 513 + 2 * i] = rtf(xe * s + xo * c);
}

__global__ void rope_q(const float* __restrict__ q, const float* __restrict__ fc,
                       float* __restrict__ qf)
{
    long idx = (long)blockIdx.x * blockDim.x + threadIdx.x;
    int i = idx & 31;
    int h = (idx >> 5) & 31;
    long r = idx >> 10;
    int pos = (int)(r & 1023);
    const float* src = q + r * 6144 + h * 192 + 128 + 2 * i;
    float xe = src[0], xo = src[1];
    float c = fc[(pos * 32 + i) * 2 + 0];
    float s = fc[(pos * 32 + i) * 2 + 1];
    float* dst = qf + (r * 32 + h) * 576 + 512 + 2 * i;
    dst[0] = rtf(xe * c - xo * s);
    dst[1] = rtf(xe * s + xo * c);
}

// softmax over causal width W; writes tf32-rounded probs
__global__ __launch_bounds__(256) void softmax_kernel(float* __restrict__ sc,
                                                      const float* __restrict__ mask)
{
    __shared__ float sh[32];
    const long m = blockIdx.x;
    const int srow = (int)((m & 32767) >> 5);
    const int W = ((srow & ~3) + 19) & ~15;
    float* p = sc + m * 1024;
    const float* mk = mask + (long)srow * 1024;
    const float scale = 0.07216878364870322f;
    const int tid = threadIdx.x;
    float l[4];
    float mx = -INFINITY;
#pragma unroll
    for (int j = 0; j < 4; j++) {
        int t = tid + j * 256;
        if (t < W) {
            l[j] = p[t] * scale + mk[t];
            mx = fmaxf(mx, l[j]);
        } else l[j] = -INFINITY;
    }
    float M = block_reduce<true>(mx, sh);
    float s = 0.f;
#pragma unroll
    for (int j = 0; j < 4; j++) {
        int t = tid + j * 256;
        if (t < W) {
            l[j] = expf(l[j] - M);
            s += l[j];
        }
    }
    float S = block_reduce<false>(s, sh);
    float inv = 1.f / S;
#pragma unroll
    for (int j = 0; j < 4; j++) {
        int t = tid + j * 256;
        if (t < W) p[t] = rtf(l[j] * inv);
    }
}

// ---------------------------------------------------------------------------
extern "C" void kernel_launch(void* const* d_in, const int* in_sizes, int n_in,
                              void* d_out, int out_size)
{
    const float* x        = (const float*)d_in[0];
    const float* fc       = (const float*)d_in[1];
    const float* mask     = (const float*)d_in[2];
    const float* wq_a     = (const float*)d_in[3];
    const float* q_norm_w = (const float*)d_in[4];
    const float* wq_b     = (const float*)d_in[5];
    const float* wkv_a    = (const float*)d_in[6];
    const float* kv_norm_w= (const float*)d_in[7];
    const float* wkv_b    = (const float*)d_in[8];
    const float* wo       = (const float*)d_in[9];
    float* out = (float*)d_out;

    float *qa, *q, *kv, *kf, *qf, *sc, *oc, *ov;
    float *xr, *w1, *w2, *w3, *w4, *w5;
    cudaGetSymbolAddress((void**)&qa, g_qa);
    cudaGetSymbolAddress((void**)&q,  g_q);
    cudaGetSymbolAddress((void**)&kv, g_kv);
    cudaGetSymbolAddress((void**)&kf, g_kf);
    cudaGetSymbolAddress((void**)&qf, g_qf);
    cudaGetSymbolAddress((void**)&sc, g_sc);
    cudaGetSymbolAddress((void**)&oc, g_oc);
    cudaGetSymbolAddress((void**)&ov, g_ov);
    cudaGetSymbolAddress((void**)&xr, g_xr);
    cudaGetSymbolAddress((void**)&w1, g_w1);
    cudaGetSymbolAddress((void**)&w2, g_w2);
    cudaGetSymbolAddress((void**)&w3, g_w3);
    cudaGetSymbolAddress((void**)&w4, g_w4);
    cudaGetSymbolAddress((void**)&w5, g_w5);

    const int SM_NT = STAGES * (BM * (BK + PAD) + BK * (BN + PAD)) * 4;
    const int SM_TB = STAGES * (BM * (BK + PAD) + BN * (BK + PAD)) * 4;
    cudaFuncSetAttribute(gemm_tc<false, false, false, false>,
                         cudaFuncAttributeMaxDynamicSharedMemorySize, SM_NT);
    cudaFuncSetAttribute(gemm_tc<false, false, false, true>,
                         cudaFuncAttributeMaxDynamicSharedMemorySize, SM_NT);
    cudaFuncSetAttribute(gemm_tc<true, true, false, false>,
                         cudaFuncAttributeMaxDynamicSharedMemorySize, SM_TB);
    cudaFuncSetAttribute(gemm_tc<false, false, true, true>,
                         cudaFuncAttributeMaxDynamicSharedMemorySize, SM_NT);
    cudaFuncSetAttribute(gemm_tc<true, false, false, true>,
                         cudaFuncAttributeMaxDynamicSharedMemorySize, SM_TB);

    const dim3 blk(256);

    // 0. tf32-round x + weights
    auto rnd = [&](const float* src, float* dst, long n) {
        long n4 = n / 4;
        round_tf32<<<(int)((n4 + 255) / 256), 256>>>(src, dst, n4);
    };
    rnd(x,     xr, 2048L * 4096);
    rnd(wq_a,  w1, 4096L * 1536);
    rnd(wq_b,  w2, 1536L * 6144);
    rnd(wkv_a, w3, 4096L * 576);
    rnd(wkv_b, w4, 32L * 256 * 512);
    rnd(wo,    w5, 4096L * 4096);

    // 1. qa = x @ wq_a   (feeds rmsnorm -> no round)
    gemm_tc<false, false, false, false><<<dim3(12, 16, 1), blk, SM_NT>>>(
        xr, w1, qa, 2048, 1536, 4096, 4096, 1536, 1536, 0, 0, 0);
    // 2. rmsnorm qa (rounded)
    rmsnorm_kernel<<<2048, 256>>>(qa, q_norm_w, qa, 1536, 1536, 1536);
    // 3. q = qa @ wq_b (rounded: feeds rope_q + gemm7)
    gemm_tc<false, false, false, true><<<dim3(48, 16, 1), blk, SM_NT>>>(
        qa, w2, q, 2048, 6144, 1536, 1536, 6144, 6144, 0, 0, 0);
    // 4. kv = x @ wkv_a (no round)
    gemm_tc<false, false, false, false><<<dim3(5, 16, 1), blk, SM_NT>>>(
        xr, w3, kv, 2048, 576, 4096, 4096, 576, 576, 0, 0, 0);
    // 5. k_full (rounded)
    rmsnorm_kernel<<<2048, 256>>>(kv, kv_norm_w, kf, 512, 576, 576);
    rope_k<<<256, 256>>>(kv, fc, kf);
    // 6. q_pe rope (rounded)
    rope_q<<<2048, 1024>>>(q, fc, qf);
    // 7. q absorb (rounded, z = h)
    gemm_tc<false, false, false, true><<<dim3(4, 16, 32), blk, SM_NT>>>(
        q, w4, qf, 2048, 512, 128, 6144, 512, 32 * 576,
        192, 256L * 512, 576);
    // 8. scores (z = b, TB, causal skip; no round)
    gemm_tc<true, true, false, false><<<dim3(8, 256, 2), blk, SM_TB>>>(
        qf, kf, sc, 32768, 1024, 576, 576, 576, 1024,
        32768L * 576, 1024L * 576, 32768L * 1024);
    // 9. softmax (causal width, rounded probs)
    softmax_kernel<<<65536, 256>>>(sc, mask);
    // 10. PV (z = b, causal K clamp, rounded)
    gemm_tc<false, false, true, true><<<dim3(4, 256, 2), blk, SM_NT>>>(
        sc, kf, oc, 32768, 512, 1024, 1024, 576, 512,
        32768L * 1024, 1024L * 576, 32768L * 512);
    // 11. v proj (z = h, TB, rounded)
    gemm_tc<true, false, false, true><<<dim3(1, 16, 32), blk, SM_TB>>>(
        oc, w4 + 128 * 512, ov, 2048, 128, 512, 32 * 512, 512, 4096,
        512, 256L * 512, 128);
    // 12. out = ov @ wo (final, no round)
    gemm_tc<false, false, false, false><<<dim3(32, 16, 1), blk, SM_NT>>>(
        ov, w5, out, 2048, 4096, 4096, 4096, 4096, 4096, 0, 0, 0);
}

// round 10
// speedup vs baseline: 4.2336x; 1.1024x over previous
#include <cuda_runtime.h>
#include <cuda_bf16.h>
#include <cstdint>
#include <math.h>

// ---------------------------------------------------------------------------
// MLA forward. tf32 mma.sync GEMMs, ldmatrix fragment loads, pre-rounded
// inputs, 4-stage cp.async, causal skipping.
// ---------------------------------------------------------------------------

static constexpr int BM = 128, BN = 128, BK = 16, PAD = 4, STAGES = 4;
static constexpr int BPAD_NT = 8;   // Bs stride 136 for !TB (conflict-free)

// scratch
__device__ __align__(256) float g_qa[2048L * 1536];
__device__ __align__(256) float g_q [2048L * 6144];
__device__ __align__(256) float g_kv[2048L * 576];
__device__ __align__(256) float g_kf[2048L * 576];
__device__ __align__(256) float g_qf[2048L * 32 * 576];
__device__ __align__(256) float g_sc[2L * 32768 * 1024];
__device__ __align__(256) float g_oc[2048L * 32 * 512];
__device__ __align__(256) float g_ov[2048L * 4096];
// tf32-rounded copies of inputs
__device__ __align__(256) float g_xr [2048L * 4096];
__device__ __align__(256) float g_w1 [4096L * 1536];
__device__ __align__(256) float g_w2 [1536L * 6144];
__device__ __align__(256) float g_w3 [4096L * 576];
__device__ __align__(256) float g_w4 [32L * 256 * 512];
__device__ __align__(256) float g_w5 [4096L * 4096];

__device__ __forceinline__ uint32_t f2tf(float f) {
    uint32_t u;
    asm("cvt.rna.tf32.f32 %0, %1;" : "=r"(u) : "f"(f));
    return u;
}
__device__ __forceinline__ float rtf(float f) { return __uint_as_float(f2tf(f)); }

__device__ __forceinline__ void cpa16(uint32_t smem, const float* g, bool pred) {
    int sz = pred ? 16 : 0;
    asm volatile("cp.async.cg.shared.global [%0], [%1], 16, %2;\n"
                 :: "r"(smem), "l"(g), "r"(sz));
}
__device__ __forceinline__ void cpa_commit() { asm volatile("cp.async.commit_group;\n"); }
template <int N> __device__ __forceinline__ void cpa_wait() {
    asm volatile("cp.async.wait_group %0;\n" :: "n"(N));
}

__device__ __forceinline__ uint32_t smem_u32(const void* p) {
    return (uint32_t)__cvta_generic_to_shared(p);
}

__device__ __forceinline__ void ldm4(uint32_t& r0, uint32_t& r1, uint32_t& r2,
                                     uint32_t& r3, uint32_t addr) {
    asm volatile("ldmatrix.sync.aligned.m8n8.x4.shared.b16 {%0,%1,%2,%3}, [%4];"
                 : "=r"(r0), "=r"(r1), "=r"(r2), "=r"(r3) : "r"(addr));
}

__device__ __forceinline__ void mma_tf32(float c[4], uint32_t a0, uint32_t a1,
                                         uint32_t a2, uint32_t a3,
                                         uint32_t b0, uint32_t b1) {
    asm volatile(
        "mma.sync.aligned.m16n8k8.row.col.f32.tf32.tf32.f32 "
        "{%0,%1,%2,%3},{%4,%5,%6,%7},{%8,%9},{%0,%1,%2,%3};\n"
        : "+f"(c[0]), "+f"(c[1]), "+f"(c[2]), "+f"(c[3])
        : "r"(a0), "r"(a1), "r"(a2), "r"(a3), "r"(b0), "r"(b1));
}

// elementwise tf32 rounding pass (n % 4 == 0)
__global__ void round_tf32(const float* __restrict__ in, float* __restrict__ out, long n4)
{
    long i = (long)blockIdx.x * blockDim.x + threadIdx.x;
    if (i < n4) {
        float4 v = reinterpret_cast<const float4*>(in)[i];
        v.x = rtf(v.x); v.y = rtf(v.y); v.z = rtf(v.z); v.w = rtf(v.w);
        reinterpret_cast<float4*>(out)[i] = v;
    }
}

// ---------------------------------------------------------------------------
// C = A @ B (or A @ B^T if TB). Inputs assumed tf32-rounded.
// RND: round C on store. CN: causal CTA skip. CK: causal K clamp.
// ---------------------------------------------------------------------------
template <bool TB, bool CN, bool CK, bool RND>
__global__ __launch_bounds__(256, 2) void gemm_tc(
    const float* __restrict__ A, const float* __restrict__ B,
    float* __restrict__ C, int M, int N, int K,
    int lda, int ldb, int ldc, long sA, long sB, long sC)
{
    constexpr int BROWS = TB ? BN : BK;
    constexpr int BCOLS = TB ? (BK + PAD) : (BN + BPAD_NT);
    extern __shared__ __align__(16) float dyn[];
    float (*As)[BM][BK + PAD] = reinterpret_cast<float(*)[BM][BK + PAD]>(dyn);
    float (*Bs)[BROWS][BCOLS] =
        reinterpret_cast<float(*)[BROWS][BCOLS]>(dyn + STAGES * BM * (BK + PAD));

    const int n0 = blockIdx.x * BN;
    const int m0 = blockIdx.y * BM;
    const int W  = ((m0 >> 5) + 19) & ~15;
    if (CN && n0 >= W) return;
    const int Keff = CK ? (W < K ? W : K) : K;

    A += (long)blockIdx.z * sA;
    B += (long)blockIdx.z * sB;
    C += (long)blockIdx.z * sC;
    const int tid = threadIdx.x;
    const int warp = tid >> 5, lane = tid & 31;
    const int wm = warp & 1, wn = warp >> 1;
    const int m0w = wm * 64, n0w = wn * 32;
    const int g = lane >> 2, t = lane & 3;

    // ldmatrix per-lane source rows/cols
    const int ar   = lane & 15;            // row within 16-row m-tile
    const int asel = (lane >> 4) * 4;      // k offset 0 or 4
    const int br   = (lane & 7) + ((lane >> 4) << 3);  // row within 16-row n-pair
    const int bsel = ((lane >> 3) & 1) * 4;            // k offset 0 or 4

    float acc[4][4][4];
#pragma unroll
    for (int i = 0; i < 4; i++)
#pragma unroll
        for (int j = 0; j < 4; j++)
#pragma unroll
            for (int r = 0; r < 4; r++) acc[i][j][r] = 0.f;

    const int KT = Keff / BK;

    auto load_stage = [&](int st, int k0) {
#pragma unroll
        for (int c = tid; c < 512; c += 256) {
            int row = c >> 2, kc = (c & 3) * 4;
            uint32_t d = smem_u32(&As[st][row][kc]);
            cpa16(d, A + (long)(m0 + row) * lda + k0 + kc, true);
        }
        if (!TB) {
#pragma unroll
            for (int c = tid; c < 512; c += 256) {
                int row = c >> 5, col = (c & 31) * 4;
                bool v = (n0 + col) < N;
                uint32_t d = smem_u32(&Bs[st][row][col]);
                cpa16(d, B + (long)(k0 + row) * ldb + n0 + col, v);
            }
        } else {
#pragma unroll
            for (int c = tid; c < 512; c += 256) {
                int row = c >> 2, kc = (c & 3) * 4;
                bool v = (n0 + row) < N;
                uint32_t d = smem_u32(&Bs[st][row][kc]);
                cpa16(d, B + (long)(n0 + row) * ldb + k0 + kc, v);
            }
        }
        cpa_commit();
    };

    load_stage(0, 0);
    if (KT > 1) load_stage(1, BK); else cpa_commit();
    if (KT > 2) load_stage(2, 2 * BK); else cpa_commit();

    for (int kt = 0; kt < KT; ++kt) {
        cpa_wait<2>();
        __syncthreads();
        if (kt + 3 < KT) load_stage((kt + 3) & 3, (kt + 3) * BK);
        else cpa_commit();
        const int st = kt & 3;

#pragma unroll
        for (int ks = 0; ks < 2; ks++) {
            const int kk = ks * 8;
            uint32_t af[4][4], bf[4][2];
            // A fragments: one ldmatrix.x4 per 16-row m-tile
#pragma unroll
            for (int mt = 0; mt < 4; mt++) {
                ldm4(af[mt][0], af[mt][1], af[mt][2], af[mt][3],
                     smem_u32(&As[st][m0w + mt * 16 + ar][kk + asel]));
            }
            if (TB) {
                // B fragments: one ldmatrix.x4 per 16-row n-pair
#pragma unroll
                for (int ntp = 0; ntp < 2; ntp++) {
                    ldm4(bf[2 * ntp][0], bf[2 * ntp][1],
                         bf[2 * ntp + 1][0], bf[2 * ntp + 1][1],
                         smem_u32(&Bs[st][n0w + ntp * 16 + br][kk + bsel]));
                }
            } else {
#pragma unroll
                for (int nt = 0; nt < 4; nt++) {
                    const int nc = n0w + nt * 8 + g;
                    bf[nt][0] = __float_as_uint(Bs[st][kk + t][nc]);
                    bf[nt][1] = __float_as_uint(Bs[st][kk + t + 4][nc]);
                }
            }
#pragma unroll
            for (int mt = 0; mt < 4; mt++)
#pragma unroll
                for (int nt = 0; nt < 4; nt++)
                    mma_tf32(acc[mt][nt], af[mt][0], af[mt][1], af[mt][2], af[mt][3],
                             bf[nt][0], bf[nt][1]);
        }
    }

    // epilogue
#pragma unroll
    for (int mt = 0; mt < 4; mt++) {
        const int mr = m0 + m0w + mt * 16 + g;
        float* Cp0 = C + (long)mr * ldc;
        float* Cp1 = C + (long)(mr + 8) * ldc;
#pragma unroll
        for (int nt = 0; nt < 4; nt++) {
            int gn = n0 + n0w + nt * 8 + t * 2;
            if (gn < N) {
                float4 v = make_float4(acc[mt][nt][0], acc[mt][nt][1],
                                       acc[mt][nt][2], acc[mt][nt][3]);
                if (RND) { v.x = rtf(v.x); v.y = rtf(v.y); v.z = rtf(v.z); v.w = rtf(v.w); }
                *reinterpret_cast<float2*>(Cp0 + gn) = make_float2(v.x, v.y);
                *reinterpret_cast<float2*>(Cp1 + gn) = make_float2(v.z, v.w);
            }
        }
    }
}

// ---------------------------------------------------------------------------
template <bool IS_MAX>
__device__ __forceinline__ float block_reduce(float v, float* sh)
{
    __syncthreads();
#pragma unroll
    for (int o = 16; o; o >>= 1) {
        float t = __shfl_xor_sync(0xffffffffu, v, o);
        v = IS_MAX ? fmaxf(v, t) : v + t;
    }
    const int lane = threadIdx.x & 31, w = threadIdx.x >> 5;
    if (lane == 0) sh[w] = v;
    __syncthreads();
    const int nw = blockDim.x >> 5;
    if (w == 0) {
        v = (lane < nw) ? sh[lane] : (IS_MAX ? -INFINITY : 0.f);
#pragma unroll
        for (int o = 16; o; o >>= 1) {
            float t = __shfl_xor_sync(0xffffffffu, v, o);
            v = IS_MAX ? fmaxf(v, t) : v + t;
        }
        if (lane == 0) sh[0] = v;
    }
    __syncthreads();
    return sh[0];
}

__global__ void rmsnorm_kernel(const float* __restrict__ in, const float* __restrict__ w,
                               float* __restrict__ out, int width, int ldin, int ldout)
{
    __shared__ float sh[32];
    const long row = blockIdx.x;
    const float* x = in + row * ldin;
    float* y = out + row * ldout;
    float ss = 0.f;
    for (int i = threadIdx.x; i < width; i += blockDim.x) {
        float v = x[i];
        ss += v * v;
    }
    float tot = block_reduce<false>(ss, sh);
    float rinv = rsqrtf(tot / (float)width + 1e-6f);
    for (int i = threadIdx.x; i < width; i += blockDim.x)
        y[i] = rtf(x[i] * rinv * w[i]);
}

__global__ void rope_k(const float* __restrict__ kv, const float* __restrict__ fc,
                       float* __restrict__ kf)
{
    int idx = blockIdx.x * blockDim.x + threadIdx.x;
    int t = idx >> 5, i = idx & 31;
    int pos = t & 1023;
    float c = fc[(pos * 32 + i) * 2 + 0];
    float s = fc[(pos * 32 + i) * 2 + 1];
    float xe = kv[(long)t * 576 + 512 + 2 * i];
    float xo = kv[(long)t * 576 + 513 + 2 * i];
    kf[(long)t * 576 + 512 + 2 * i] = rtf(xe * c - xo * s);
    kf[(long)t * 576 + 513 + 2 * i] = rtf(xe * s + xo * c);
}

__global__ void rope_q(const float* __restrict__ q, const float* __restrict__ fc,
                       float* __restrict__ qf)
{
    long idx = (long)blockIdx.x * blockDim.x + threadIdx.x;
    int i = idx & 31;
    int h = (idx >> 5) & 31;
    long r = idx >> 10;
    int pos = (int)(r & 1023);
    const float* src = q + r * 6144 + h * 192 + 128 + 2 * i;
    float xe = src[0], xo = src[1];
    float c = fc[(pos * 32 + i) * 2 + 0];
    float s = fc[(pos * 32 + i) * 2 + 1];
    float* dst = qf + (r * 32 + h) * 576 + 512 + 2 * i;
    dst[0] = rtf(xe * c - xo * s);
    dst[1] = rtf(xe * s + xo * c);
}

// softmax over causal width W; writes tf32-rounded probs
__global__ __launch_bounds__(256) void softmax_kernel(float* __restrict__ sc,
                                                      const float* __restrict__ mask)
{
    __shared__ float sh[32];
    const long m = blockIdx.x;
    const int srow = (int)((m & 32767) >> 5);
    const int W = ((srow & ~3) + 19) & ~15;
    float* p = sc + m * 1024;
    const float* mk = mask + (long)srow * 1024;
    const float scale = 0.07216878364870322f;
    const int tid = threadIdx.x;
    float l[4];
    float mx = -INFINITY;
#pragma unroll
    for (int j = 0; j < 4; j++) {
        int t = tid + j * 256;
        if (t < W) {
            l[j] = p[t] * scale + mk[t];
            mx = fmaxf(mx, l[j]);
        } else l[j] = -INFINITY;
    }
    float M = block_reduce<true>(mx, sh);
    float s = 0.f;
#pragma unroll
    for (int j = 0; j < 4; j++) {
        int t = tid + j * 256;
        if (t < W) {
            l[j] = expf(l[j] - M);
            s += l[j];
        }
    }
    float S = block_reduce<false>(s, sh);
    float inv = 1.f / S;
#pragma unroll
    for (int j = 0; j < 4; j++) {
        int t = tid + j * 256;
        if (t < W) p[t] = rtf(l[j] * inv);
    }
}

// ---------------------------------------------------------------------------
extern "C" void kernel_launch(void* const* d_in, const int* in_sizes, int n_in,
                              void* d_out, int out_size)
{
    const float* x        = (const float*)d_in[0];
    const float* fc       = (const float*)d_in[1];
    const float* mask     = (const float*)d_in[2];
    const float* wq_a     = (const float*)d_in[3];
    const float* q_norm_w = (const float*)d_in[4];
    const float* wq_b     = (const float*)d_in[5];
    const float* wkv_a    = (const float*)d_in[6];
    const float* kv_norm_w= (const float*)d_in[7];
    const float* wkv_b    = (const float*)d_in[8];
    const float* wo       = (const float*)d_in[9];
    float* out = (float*)d_out;

    float *qa, *q, *kv, *kf, *qf, *sc, *oc, *ov;
    float *xr, *w1, *w2, *w3, *w4, *w5;
    cudaGetSymbolAddress((void**)&qa, g_qa);
    cudaGetSymbolAddress((void**)&q,  g_q);
    cudaGetSymbolAddress((void**)&kv, g_kv);
    cudaGetSymbolAddress((void**)&kf, g_kf);
    cudaGetSymbolAddress((void**)&qf, g_qf);
    cudaGetSymbolAddress((void**)&sc, g_sc);
    cudaGetSymbolAddress((void**)&oc, g_oc);
    cudaGetSymbolAddress((void**)&ov, g_ov);
    cudaGetSymbolAddress((void**)&xr, g_xr);
    cudaGetSymbolAddress((void**)&w1, g_w1);
    cudaGetSymbolAddress((void**)&w2, g_w2);
    cudaGetSymbolAddress((void**)&w3, g_w3);
    cudaGetSymbolAddress((void**)&w4, g_w4);
    cudaGetSymbolAddress((void**)&w5, g_w5);

    const int SM_NT = STAGES * (BM * (BK + PAD) + BK * (BN + BPAD_NT)) * 4;
    const int SM_TB = STAGES * (BM * (BK + PAD) + BN * (BK + PAD)) * 4;
    cudaFuncSetAttribute(gemm_tc<false, false, false, false>,
                         cudaFuncAttributeMaxDynamicSharedMemorySize, SM_NT);
    cudaFuncSetAttribute(gemm_tc<false, false, false, true>,
                         cudaFuncAttributeMaxDynamicSharedMemorySize, SM_NT);
    cudaFuncSetAttribute(gemm_tc<true, true, false, false>,
                         cudaFuncAttributeMaxDynamicSharedMemorySize, SM_TB);
    cudaFuncSetAttribute(gemm_tc<false, false, true, true>,
                         cudaFuncAttributeMaxDynamicSharedMemorySize, SM_NT);
    cudaFuncSetAttribute(gemm_tc<true, false, false, true>,
                         cudaFuncAttributeMaxDynamicSharedMemorySize, SM_TB);

    const dim3 blk(256);

    // 0. tf32-round x + weights
    auto rnd = [&](const float* src, float* dst, long n) {
        long n4 = n / 4;
        round_tf32<<<(int)((n4 + 255) / 256), 256>>>(src, dst, n4);
    };
    rnd(x,     xr, 2048L * 4096);
    rnd(wq_a,  w1, 4096L * 1536);
    rnd(wq_b,  w2, 1536L * 6144);
    rnd(wkv_a, w3, 4096L * 576);
    rnd(wkv_b, w4, 32L * 256 * 512);
    rnd(wo,    w5, 4096L * 4096);

    // 1. qa = x @ wq_a
    gemm_tc<false, false, false, false><<<dim3(12, 16, 1), blk, SM_NT>>>(
        xr, w1, qa, 2048, 1536, 4096, 4096, 1536, 1536, 0, 0, 0);
    // 2. rmsnorm qa
    rmsnorm_kernel<<<2048, 256>>>(qa, q_norm_w, qa, 1536, 1536, 1536);
    // 3. q = qa @ wq_b
    gemm_tc<false, false, false, true><<<dim3(48, 16, 1), blk, SM_NT>>>(
        qa, w2, q, 2048, 6144, 1536, 1536, 6144, 6144, 0, 0, 0);
    // 4. kv = x @ wkv_a
    gemm_tc<false, false, false, false><<<dim3(5, 16, 1), blk, SM_NT>>>(
        xr, w3, kv, 2048, 576, 4096, 4096, 576, 576, 0, 0, 0);
    // 5. k_full
    rmsnorm_kernel<<<2048, 256>>>(kv, kv_norm_w, kf, 512, 576, 576);
    rope_k<<<256, 256>>>(kv, fc, kf);
    // 6. q_pe rope
    rope_q<<<2048, 1024>>>(q, fc, qf);
    // 7. q absorb (z = h)
    gemm_tc<false, false, false, true><<<dim3(4, 16, 32), blk, SM_NT>>>(
        q, w4, qf, 2048, 512, 128, 6144, 512, 32 * 576,
        192, 256L * 512, 576);
    // 8. scores (z = b, TB, causal skip)
    gemm_tc<true, true, false, false><<<dim3(8, 256, 2), blk, SM_TB>>>(
        qf, kf, sc, 32768, 1024, 576, 576, 576, 1024,
        32768L * 576, 1024L * 576, 32768L * 1024);
    // 9. softmax
    softmax_kernel<<<65536, 256>>>(sc, mask);
    // 10. PV (z = b, causal K clamp)
    gemm_tc<false, false, true, true><<<dim3(4, 256, 2), blk, SM_NT>>>(
        sc, kf, oc, 32768, 512, 1024, 1024, 576, 512,
        32768L * 1024, 1024L * 576, 32768L * 512);
    // 11. v proj (z = h, TB)
    gemm_tc<true, false, false, true><<<dim3(1, 16, 32), blk, SM_TB>>>(
        oc, w4 + 128 * 512, ov, 2048, 128, 512, 32 * 512, 512, 4096,
        512, 256L * 512, 128);
    // 12. out = ov @ wo
    gemm_tc<false, false, false, false><<<dim3(32, 16, 1), blk, SM_NT>>>(
        ov, w5, out, 2048, 4096, 4096, 4096, 4096, 4096, 0, 0, 0);
}

// round 12
// speedup vs baseline: 4.5588x; 1.0768x over previous
#include <cuda_runtime.h>
#include <cuda_bf16.h>
#include <cstdint>
#include <math.h>

// ---------------------------------------------------------------------------
// MLA forward. tf32 mma.sync GEMMs, ldmatrix fragments, pre-rounded inputs,
// 4-stage cp.async, causal skipping. R11: fused qa/kv GEMM + wide softmax.
//  0. round x; round [wq_a | wkv_a] into w13; round wq_b, wkv_b, wo
//  1. qkv = x @ [wq_a | wkv_a]        (one GEMM, N=2112)
//  2. qa = rmsnorm(qkv[:, :1536])
//  3. q  = qa @ wq_b
//  5. kf = [rmsnorm(qkv[:,1536:2048]) | rope(qkv[:,2048:2112])]
//  6. qf[:,512:576] = rope(q_pe)
//  7. qf[:,0:512]   = q_nope @ wkv_b[h,:128,:]      (z=h)
//  8. sc[b] = qf[b] @ kf[b]^T   (causal skip)
//  9. softmax(sc*SCALE + mask)  (one block per (b,s), 32 rows)
// 10. oc[b] = sc[b] @ kf[b][:,0:512]   (causal K clamp)
// 11. ov = oc @ wkv_b[h,128:,:]^T      (z=h, TB)
// 12. out = ov @ wo
// ---------------------------------------------------------------------------

static constexpr int BM = 128, BN = 128, BK = 16, PAD = 4, STAGES = 4;
static constexpr int BPAD_NT = 8;

// scratch
__device__ __align__(256) float g_qkv[2048L * 2112];
__device__ __align__(256) float g_qa[2048L * 1536];
__device__ __align__(256) float g_q [2048L * 6144];
__device__ __align__(256) float g_kf[2048L * 576];
__device__ __align__(256) float g_qf[2048L * 32 * 576];
__device__ __align__(256) float g_sc[2L * 32768 * 1024];
__device__ __align__(256) float g_oc[2048L * 32 * 512];
__device__ __align__(256) float g_ov[2048L * 4096];
// tf32-rounded inputs
__device__ __align__(256) float g_xr [2048L * 4096];
__device__ __align__(256) float g_w13[4096L * 2112];   // [wq_a | wkv_a]
__device__ __align__(256) float g_w2 [1536L * 6144];   // wq_b
__device__ __align__(256) float g_w4 [32L * 256 * 512];// wkv_b
__device__ __align__(256) float g_w5 [4096L * 4096];   // wo

__device__ __forceinline__ uint32_t f2tf(float f) {
    uint32_t u;
    asm("cvt.rna.tf32.f32 %0, %1;" : "=r"(u) : "f"(f));
    return u;
}
__device__ __forceinline__ float rtf(float f) { return __uint_as_float(f2tf(f)); }

__device__ __forceinline__ void cpa16(uint32_t smem, const float* g, bool pred) {
    int sz = pred ? 16 : 0;
    asm volatile("cp.async.cg.shared.global [%0], [%1], 16, %2;\n"
                 :: "r"(smem), "l"(g), "r"(sz));
}
__device__ __forceinline__ void cpa_commit() { asm volatile("cp.async.commit_group;\n"); }
template <int N> __device__ __forceinline__ void cpa_wait() {
    asm volatile("cp.async.wait_group %0;\n" :: "n"(N));
}
__device__ __forceinline__ uint32_t smem_u32(const void* p) {
    return (uint32_t)__cvta_generic_to_shared(p);
}
__device__ __forceinline__ void ldm4(uint32_t& r0, uint32_t& r1, uint32_t& r2,
                                     uint32_t& r3, uint32_t addr) {
    asm volatile("ldmatrix.sync.aligned.m8n8.x4.shared.b16 {%0,%1,%2,%3}, [%4];"
                 : "=r"(r0), "=r"(r1), "=r"(r2), "=r"(r3) : "r"(addr));
}
__device__ __forceinline__ void mma_tf32(float c[4], uint32_t a0, uint32_t a1,
                                         uint32_t a2, uint32_t a3,
                                         uint32_t b0, uint32_t b1) {
    asm volatile(
        "mma.sync.aligned.m16n8k8.row.col.f32.tf32.tf32.f32 "
        "{%0,%1,%2,%3},{%4,%5,%6,%7},{%8,%9},{%0,%1,%2,%3};\n"
        : "+f"(c[0]), "+f"(c[1]), "+f"(c[2]), "+f"(c[3])
        : "r"(a0), "r"(a1), "r"(a2), "r"(a3), "r"(b0), "r"(b1));
}

// plain tf32 rounding (n % 4 == 0)
__global__ void round_tf32(const float* __restrict__ in, float* __restrict__ out, long n4)
{
    long i = (long)blockIdx.x * blockDim.x + threadIdx.x;
    if (i < n4) {
        float4 v = reinterpret_cast<const float4*>(in)[i];
        v.x = rtf(v.x); v.y = rtf(v.y); v.z = rtf(v.z); v.w = rtf(v.w);
        reinterpret_cast<float4*>(out)[i] = v;
    }
}

// strided rounding: src [rows, cols] dense -> dst rows with leading dim ld,
// starting at column off. cols % 4 == 0.
__global__ void round_tf32_str(const float* __restrict__ in, float* __restrict__ out,
                               long rows, int cols, int ld, int off)
{
    long n4 = rows * (cols / 4);
    long i = (long)blockIdx.x * blockDim.x + threadIdx.x;
    if (i < n4) {
        int c4 = (int)(i % (cols / 4));
        long r = i / (cols / 4);
        float4 v = reinterpret_cast<const float4*>(in + r * cols)[c4];
        v.x = rtf(v.x); v.y = rtf(v.y); v.z = rtf(v.z); v.w = rtf(v.w);
        *reinterpret_cast<float4*>(out + r * ld + off + c4 * 4) = v;
    }
}

// ---------------------------------------------------------------------------
// C = A @ B (or A @ B^T if TB). Inputs assumed tf32-rounded.
// ---------------------------------------------------------------------------
template <bool TB, bool CN, bool CK, bool RND>
__global__ __launch_bounds__(256, 2) void gemm_tc(
    const float* __restrict__ A, const float* __restrict__ B,
    float* __restrict__ C, int M, int N, int K,
    int lda, int ldb, int ldc, long sA, long sB, long sC)
{
    constexpr int BROWS = TB ? BN : BK;
    constexpr int BCOLS = TB ? (BK + PAD) : (BN + BPAD_NT);
    extern __shared__ __align__(16) float dyn[];
    float (*As)[BM][BK + PAD] = reinterpret_cast<float(*)[BM][BK + PAD]>(dyn);
    float (*Bs)[BROWS][BCOLS] =
        reinterpret_cast<float(*)[BROWS][BCOLS]>(dyn + STAGES * BM * (BK + PAD));

    const int n0 = blockIdx.x * BN;
    const int m0 = blockIdx.y * BM;
    const int W  = ((m0 >> 5) + 19) & ~15;
    if (CN && n0 >= W) return;
    const int Keff = CK ? (W < K ? W : K) : K;

    A += (long)blockIdx.z * sA;
    B += (long)blockIdx.z * sB;
    C += (long)blockIdx.z * sC;
    const int tid = threadIdx.x;
    const int warp = tid >> 5, lane = tid & 31;
    const int wm = warp & 1, wn = warp >> 1;
    const int m0w = wm * 64, n0w = wn * 32;
    const int g = lane >> 2, t = lane & 3;

    const int ar   = lane & 15;
    const int asel = (lane >> 4) * 4;
    const int br   = (lane & 7) + ((lane >> 4) << 3);
    const int bsel = ((lane >> 3) & 1) * 4;

    float acc[4][4][4];
#pragma unroll
    for (int i = 0; i < 4; i++)
#pragma unroll
        for (int j = 0; j < 4; j++)
#pragma unroll
            for (int r = 0; r < 4; r++) acc[i][j][r] = 0.f;

    const int KT = Keff / BK;

    auto load_stage = [&](int st, int k0) {
#pragma unroll
        for (int c = tid; c < 512; c += 256) {
            int row = c >> 2, kc = (c & 3) * 4;
            uint32_t d = smem_u32(&As[st][row][kc]);
            cpa16(d, A + (long)(m0 + row) * lda + k0 + kc, true);
        }
        if (!TB) {
#pragma unroll
            for (int c = tid; c < 512; c += 256) {
                int row = c >> 5, col = (c & 31) * 4;
                bool v = (n0 + col) < N;
                uint32_t d = smem_u32(&Bs[st][row][col]);
                cpa16(d, B + (long)(k0 + row) * ldb + n0 + col, v);
            }
        } else {
#pragma unroll
            for (int c = tid; c < 512; c += 256) {
                int row = c >> 2, kc = (c & 3) * 4;
                bool v = (n0 + row) < N;
                uint32_t d = smem_u32(&Bs[st][row][kc]);
                cpa16(d, B + (long)(n0 + row) * ldb + k0 + kc, v);
            }
        }
        cpa_commit();
    };

    load_stage(0, 0);
    if (KT > 1) load_stage(1, BK); else cpa_commit();
    if (KT > 2) load_stage(2, 2 * BK); else cpa_commit();

    for (int kt = 0; kt < KT; ++kt) {
        cpa_wait<2>();
        __syncthreads();
        if (kt + 3 < KT) load_stage((kt + 3) & 3, (kt + 3) * BK);
        else cpa_commit();
        const int st = kt & 3;

#pragma unroll
        for (int ks = 0; ks < 2; ks++) {
            const int kk = ks * 8;
            uint32_t af[4][4], bf[4][2];
#pragma unroll
            for (int mt = 0; mt < 4; mt++) {
                ldm4(af[mt][0], af[mt][1], af[mt][2], af[mt][3],
                     smem_u32(&As[st][m0w + mt * 16 + ar][kk + asel]));
            }
            if (TB) {
#pragma unroll
                for (int ntp = 0; ntp < 2; ntp++) {
                    ldm4(bf[2 * ntp][0], bf[2 * ntp][1],
                         bf[2 * ntp + 1][0], bf[2 * ntp + 1][1],
                         smem_u32(&Bs[st][n0w + ntp * 16 + br][kk + bsel]));
                }
            } else {
#pragma unroll
                for (int nt = 0; nt < 4; nt++) {
                    const int nc = n0w + nt * 8 + g;
                    bf[nt][0] = __float_as_uint(Bs[st][kk + t][nc]);
                    bf[nt][1] = __float_as_uint(Bs[st][kk + t + 4][nc]);
                }
            }
#pragma unroll
            for (int mt = 0; mt < 4; mt++)
#pragma unroll
                for (int nt = 0; nt < 4; nt++)
                    mma_tf32(acc[mt][nt], af[mt][0], af[mt][1], af[mt][2], af[mt][3],
                             bf[nt][0], bf[nt][1]);
        }
    }

#pragma unroll
    for (int mt = 0; mt < 4; mt++) {
        const int mr = m0 + m0w + mt * 16 + g;
        float* Cp0 = C + (long)mr * ldc;
        float* Cp1 = C + (long)(mr + 8) * ldc;
#pragma unroll
        for (int nt = 0; nt < 4; nt++) {
            int gn = n0 + n0w + nt * 8 + t * 2;
            if (gn < N) {
                float4 v = make_float4(acc[mt][nt][0], acc[mt][nt][1],
                                       acc[mt][nt][2], acc[mt][nt][3]);
                if (RND) { v.x = rtf(v.x); v.y = rtf(v.y); v.z = rtf(v.z); v.w = rtf(v.w); }
                *reinterpret_cast<float2*>(Cp0 + gn) = make_float2(v.x, v.y);
                *reinterpret_cast<float2*>(Cp1 + gn) = make_float2(v.z, v.w);
            }
        }
    }
}

// ---------------------------------------------------------------------------
template <bool IS_MAX>
__device__ __forceinline__ float block_reduce(float v, float* sh)
{
    __syncthreads();
#pragma unroll
    for (int o = 16; o; o >>= 1) {
        float t = __shfl_xor_sync(0xffffffffu, v, o);
        v = IS_MAX ? fmaxf(v, t) : v + t;
    }
    const int lane = threadIdx.x & 31, w = threadIdx.x >> 5;
    if (lane == 0) sh[w] = v;
    __syncthreads();
    const int nw = blockDim.x >> 5;
    if (w == 0) {
        v = (lane < nw) ? sh[lane] : (IS_MAX ? -INFINITY : 0.f);
#pragma unroll
        for (int o = 16; o; o >>= 1) {
            float t = __shfl_xor_sync(0xffffffffu, v, o);
            v = IS_MAX ? fmaxf(v, t) : v + t;
        }
        if (lane == 0) sh[0] = v;
    }
    __syncthreads();
    return sh[0];
}

__global__ void rmsnorm_kernel(const float* __restrict__ in, const float* __restrict__ w,
                               float* __restrict__ out, int width, int ldin, int ldout)
{
    __shared__ float sh[32];
    const long row = blockIdx.x;
    const float* x = in + row * ldin;
    float* y = out + row * ldout;
    float ss = 0.f;
    for (int i = threadIdx.x; i < width; i += blockDim.x) {
        float v = x[i];
        ss += v * v;
    }
    float tot = block_reduce<false>(ss, sh);
    float rinv = rsqrtf(tot / (float)width + 1e-6f);
    for (int i = threadIdx.x; i < width; i += blockDim.x)
        y[i] = rtf(x[i] * rinv * w[i]);
}

// rope for k_pe: qkv[t, 2048:2112] -> kf[t, 512:576]
__global__ void rope_k(const float* __restrict__ qkv, const float* __restrict__ fc,
                       float* __restrict__ kf)
{
    int idx = blockIdx.x * blockDim.x + threadIdx.x;
    int t = idx >> 5, i = idx & 31;
    int pos = t & 1023;
    float c = fc[(pos * 32 + i) * 2 + 0];
    float s = fc[(pos * 32 + i) * 2 + 1];
    float xe = qkv[(long)t * 2112 + 2048 + 2 * i];
    float xo = qkv[(long)t * 2112 + 2049 + 2 * i];
    kf[(long)t * 576 + 512 + 2 * i] = rtf(xe * c - xo * s);
    kf[(long)t * 576 + 513 + 2 * i] = rtf(xe * s + xo * c);
}

__global__ void rope_q(const float* __restrict__ q, const float* __restrict__ fc,
                       float* __restrict__ qf)
{
    long idx = (long)blockIdx.x * blockDim.x + threadIdx.x;
    int i = idx & 31;
    int h = (idx >> 5) & 31;
    long r = idx >> 10;
    int pos = (int)(r & 1023);
    const float* src = q + r * 6144 + h * 192 + 128 + 2 * i;
    float xe = src[0], xo = src[1];
    float c = fc[(pos * 32 + i) * 2 + 0];
    float s = fc[(pos * 32 + i) * 2 + 1];
    float* dst = qf + (r * 32 + h) * 576 + 512 + 2 * i;
    dst[0] = rtf(xe * c - xo * s);
    dst[1] = rtf(xe * s + xo * c);
}

// softmax: one block per (b,s); 32 rows (heads), 8 threads/row.
__global__ __launch_bounds__(256) void softmax_kernel(float* __restrict__ sc,
                                                      const float* __restrict__ mask)
{
    const int bs = blockIdx.x;              // b*1024 + s
    const int b = bs >> 10, s = bs & 1023;
    const int W = ((s & ~3) + 19) & ~15;    // same W as GEMM tiles
    const int r = threadIdx.x >> 3;         // head row 0..31
    const int t = threadIdx.x & 7;          // lane within row group
    float* p = sc + ((long)b * 32768 + s * 32 + r) * 1024;
    const float* mk = mask + (long)s * 1024;
    const float scale = 0.07216878364870322f;

    float mx = -INFINITY;
    for (int j = t; j < W; j += 8)
        mx = fmaxf(mx, p[j] * scale + mk[j]);
#pragma unroll
    for (int o = 4; o; o >>= 1)
        mx = fmaxf(mx, __shfl_xor_sync(0xffffffffu, mx, o));

    float sum = 0.f;
    for (int j = t; j < W; j += 8) {
        float e = expf(p[j] * scale + mk[j] - mx);
        p[j] = e;
        sum += e;
    }
#pragma unroll
    for (int o = 4; o; o >>= 1)
        sum += __shfl_xor_sync(0xffffffffu, sum, o);
    float inv = 1.f / sum;
    for (int j = t; j < W; j += 8)
        p[j] = rtf(p[j] * inv);
}

// ---------------------------------------------------------------------------
extern "C" void kernel_launch(void* const* d_in, const int* in_sizes, int n_in,
                              void* d_out, int out_size)
{
    const float* x        = (const float*)d_in[0];
    const float* fc       = (const float*)d_in[1];
    const float* mask     = (const float*)d_in[2];
    const float* wq_a     = (const float*)d_in[3];
    const float* q_norm_w = (const float*)d_in[4];
    const float* wq_b     = (const float*)d_in[5];
    const float* wkv_a    = (const float*)d_in[6];
    const float* kv_norm_w= (const float*)d_in[7];
    const float* wkv_b    = (const float*)d_in[8];
    const float* wo       = (const float*)d_in[9];
    float* out = (float*)d_out;

    float *qkv, *qa, *q, *kf, *qf, *sc, *oc, *ov;
    float *xr, *w13, *w2, *w4, *w5;
    cudaGetSymbolAddress((void**)&qkv, g_qkv);
    cudaGetSymbolAddress((void**)&qa, g_qa);
    cudaGetSymbolAddress((void**)&q,  g_q);
    cudaGetSymbolAddress((void**)&kf, g_kf);
    cudaGetSymbolAddress((void**)&qf, g_qf);
    cudaGetSymbolAddress((void**)&sc, g_sc);
    cudaGetSymbolAddress((void**)&oc, g_oc);
    cudaGetSymbolAddress((void**)&ov, g_ov);
    cudaGetSymbolAddress((void**)&xr, g_xr);
    cudaGetSymbolAddress((void**)&w13, g_w13);
    cudaGetSymbolAddress((void**)&w2, g_w2);
    cudaGetSymbolAddress((void**)&w4, g_w4);
    cudaGetSymbolAddress((void**)&w5, g_w5);

    const int SM_NT = STAGES * (BM * (BK + PAD) + BK * (BN + BPAD_NT)) * 4;
    const int SM_TB = STAGES * (BM * (BK + PAD) + BN * (BK + PAD)) * 4;
    cudaFuncSetAttribute(gemm_tc<false, false, false, false>,
                         cudaFuncAttributeMaxDynamicSharedMemorySize, SM_NT);
    cudaFuncSetAttribute(gemm_tc<false, false, false, true>,
                         cudaFuncAttributeMaxDynamicSharedMemorySize, SM_NT);
    cudaFuncSetAttribute(gemm_tc<true, true, false, false>,
                         cudaFuncAttributeMaxDynamicSharedMemorySize, SM_TB);
    cudaFuncSetAttribute(gemm_tc<false, false, true, true>,
                         cudaFuncAttributeMaxDynamicSharedMemorySize, SM_NT);
    cudaFuncSetAttribute(gemm_tc<true, false, false, true>,
                         cudaFuncAttributeMaxDynamicSharedMemorySize, SM_TB);

    const dim3 blk(256);

    // 0. tf32-round inputs
    {
        long n4 = 2048L * 4096 / 4;
        round_tf32<<<(int)((n4 + 255) / 256), 256>>>(x, xr, n4);
        n4 = 1536L * 6144 / 4;
        round_tf32<<<(int)((n4 + 255) / 256), 256>>>(wq_b, w2, n4);
        n4 = 32L * 256 * 512 / 4;
        round_tf32<<<(int)((n4 + 255) / 256), 256>>>(wkv_b, w4, n4);
        n4 = 4096L * 4096 / 4;
        round_tf32<<<(int)((n4 + 255) / 256), 256>>>(wo, w5, n4);
        // wq_a -> w13[:, 0:1536], wkv_a -> w13[:, 1536:2112]
        n4 = 4096L * 1536 / 4;
        round_tf32_str<<<(int)((n4 + 255) / 256), 256>>>(wq_a, w13, 4096, 1536, 2112, 0);
        n4 = 4096L * 576 / 4;
        round_tf32_str<<<(int)((n4 + 255) / 256), 256>>>(wkv_a, w13, 4096, 576, 2112, 1536);
    }

    // 1. qkv = x @ [wq_a | wkv_a]
    gemm_tc<false, false, false, false><<<dim3(17, 16, 1), blk, SM_NT>>>(
        xr, w13, qkv, 2048, 2112, 4096, 4096, 2112, 2112, 0, 0, 0);
    // 2. qa = rmsnorm(qkv[:, :1536])
    rmsnorm_kernel<<<2048, 256>>>(qkv, q_norm_w, qa, 1536, 2112, 1536);
    // 3. q = qa @ wq_b
    gemm_tc<false, false, false, true><<<dim3(48, 16, 1), blk, SM_NT>>>(
        qa, w2, q, 2048, 6144, 1536, 1536, 6144, 6144, 0, 0, 0);
    // 5. kf
    rmsnorm_kernel<<<2048, 256>>>(qkv + 1536, kv_norm_w, kf, 512, 2112, 576);
    rope_k<<<256, 256>>>(qkv, fc, kf);
    // 6. q_pe rope
    rope_q<<<2048, 1024>>>(q, fc, qf);
    // 7. q absorb (z = h)
    gemm_tc<false, false, false, true><<<dim3(4, 16, 32), blk, SM_NT>>>(
        q, w4, qf, 2048, 512, 128, 6144, 512, 32 * 576,
        192, 256L * 512, 576);
    // 8. scores (z = b, TB, causal skip)
    gemm_tc<true, true, false, false><<<dim3(8, 256, 2), blk, SM_TB>>>(
        qf, kf, sc, 32768, 1024, 576, 576, 576, 1024,
        32768L * 576, 1024L * 576, 32768L * 1024);
    // 9. softmax
    softmax_kernel<<<2048, 256>>>(sc, mask);
    // 10. PV (z = b, causal K clamp)
    gemm_tc<false, false, true, true><<<dim3(4, 256, 2), blk, SM_NT>>>(
        sc, kf, oc, 32768, 512, 1024, 1024, 576, 512,
        32768L * 1024, 1024L * 576, 32768L * 512);
    // 11. v proj (z = h, TB)
    gemm_tc<true, false, false, true><<<dim3(1, 16, 32), blk, SM_TB>>>(
        oc, w4 + 128 * 512, ov, 2048, 128, 512, 32 * 512, 512, 4096,
        512, 256L * 512, 128);
    // 12. out = ov @ wo
    gemm_tc<false, false, false, false><<<dim3(32, 16, 1), blk, SM_NT>>>(
        ov, w5, out, 2048, 4096, 4096, 4096, 4096, 4096, 0, 0, 0);
}

// round 13
// speedup vs baseline: 5.4804x; 1.2022x over previous
#include <cuda_runtime.h>
#include <cuda_bf16.h>
#include <cstdint>
#include <math.h>

// ---------------------------------------------------------------------------
// MLA forward. tf32 mma.sync GEMMs (64x64 warp tiles), ldmatrix fragments,
// pre-rounded inputs, 4-stage cp.async, causal skipping, fused qa/kv GEMM.
// ---------------------------------------------------------------------------

static constexpr int BM = 128, BN = 128, BK = 16, PAD = 4, STAGES = 4;
static constexpr int BPAD_NT = 8;

// scratch
__device__ __align__(256) float g_qkv[2048L * 2112];
__device__ __align__(256) float g_qa[2048L * 1536];
__device__ __align__(256) float g_q [2048L * 6144];
__device__ __align__(256) float g_kf[2048L * 576];
__device__ __align__(256) float g_qf[2048L * 32 * 576];
__device__ __align__(256) float g_sc[2L * 32768 * 1024];
__device__ __align__(256) float g_oc[2048L * 32 * 512];
__device__ __align__(256) float g_ov[2048L * 4096];
// tf32-rounded inputs
__device__ __align__(256) float g_xr [2048L * 4096];
__device__ __align__(256) float g_w13[4096L * 2112];
__device__ __align__(256) float g_w2 [1536L * 6144];
__device__ __align__(256) float g_w4 [32L * 256 * 512];
__device__ __align__(256) float g_w5 [4096L * 4096];

__device__ __forceinline__ uint32_t f2tf(float f) {
    uint32_t u;
    asm("cvt.rna.tf32.f32 %0, %1;" : "=r"(u) : "f"(f));
    return u;
}
__device__ __forceinline__ float rtf(float f) { return __uint_as_float(f2tf(f)); }

__device__ __forceinline__ void cpa16(uint32_t smem, const float* g, bool pred) {
    int sz = pred ? 16 : 0;
    asm volatile("cp.async.cg.shared.global [%0], [%1], 16, %2;\n"
                 :: "r"(smem), "l"(g), "r"(sz));
}
__device__ __forceinline__ void cpa_commit() { asm volatile("cp.async.commit_group;\n"); }
template <int N> __device__ __forceinline__ void cpa_wait() {
    asm volatile("cp.async.wait_group %0;\n" :: "n"(N));
}
__device__ __forceinline__ uint32_t smem_u32(const void* p) {
    return (uint32_t)__cvta_generic_to_shared(p);
}
__device__ __forceinline__ void ldm4(uint32_t& r0, uint32_t& r1, uint32_t& r2,
                                     uint32_t& r3, uint32_t addr) {
    asm volatile("ldmatrix.sync.aligned.m8n8.x4.shared.b16 {%0,%1,%2,%3}, [%4];"
                 : "=r"(r0), "=r"(r1), "=r"(r2), "=r"(r3) : "r"(addr));
}
__device__ __forceinline__ void mma_tf32(float c[4], uint32_t a0, uint32_t a1,
                                         uint32_t a2, uint32_t a3,
                                         uint32_t b0, uint32_t b1) {
    asm volatile(
        "mma.sync.aligned.m16n8k8.row.col.f32.tf32.tf32.f32 "
        "{%0,%1,%2,%3},{%4,%5,%6,%7},{%8,%9},{%0,%1,%2,%3};\n"
        : "+f"(c[0]), "+f"(c[1]), "+f"(c[2]), "+f"(c[3])
        : "r"(a0), "r"(a1), "r"(a2), "r"(a3), "r"(b0), "r"(b1));
}

// plain tf32 rounding (n % 4 == 0)
__global__ void round_tf32(const float* __restrict__ in, float* __restrict__ out, long n4)
{
    long i = (long)blockIdx.x * blockDim.x + threadIdx.x;
    if (i < n4) {
        float4 v = reinterpret_cast<const float4*>(in)[i];
        v.x = rtf(v.x); v.y = rtf(v.y); v.z = rtf(v.z); v.w = rtf(v.w);
        reinterpret_cast<float4*>(out)[i] = v;
    }
}

// strided rounding into column block [off, off+cols) of dst with leading dim ld
__global__ void round_tf32_str(const float* __restrict__ in, float* __restrict__ out,
                               long rows, int cols, int ld, int off)
{
    long n4 = rows * (cols / 4);
    long i = (long)blockIdx.x * blockDim.x + threadIdx.x;
    if (i < n4) {
        int c4 = (int)(i % (cols / 4));
        long r = i / (cols / 4);
        float4 v = reinterpret_cast<const float4*>(in + r * cols)[c4];
        v.x = rtf(v.x); v.y = rtf(v.y); v.z = rtf(v.z); v.w = rtf(v.w);
        *reinterpret_cast<float4*>(out + r * ld + off + c4 * 4) = v;
    }
}

// ---------------------------------------------------------------------------
// C = A @ B (or A @ B^T if TB). 128 threads, 4 warps, 64x64 warp tiles.
// ---------------------------------------------------------------------------
template <bool TB, bool CN, bool CK, bool RND>
__global__ __launch_bounds__(128, 2) void gemm_tc(
    const float* __restrict__ A, const float* __restrict__ B,
    float* __restrict__ C, int M, int N, int K,
    int lda, int ldb, int ldc, long sA, long sB, long sC)
{
    constexpr int BROWS = TB ? BN : BK;
    constexpr int BCOLS = TB ? (BK + PAD) : (BN + BPAD_NT);
    extern __shared__ __align__(16) float dyn[];
    float (*As)[BM][BK + PAD] = reinterpret_cast<float(*)[BM][BK + PAD]>(dyn);
    float (*Bs)[BROWS][BCOLS] =
        reinterpret_cast<float(*)[BROWS][BCOLS]>(dyn + STAGES * BM * (BK + PAD));

    const int n0 = blockIdx.x * BN;
    const int m0 = blockIdx.y * BM;
    const int W  = ((m0 >> 5) + 19) & ~15;
    if (CN && n0 >= W) return;
    const int Keff = CK ? (W < K ? W : K) : K;

    A += (long)blockIdx.z * sA;
    B += (long)blockIdx.z * sB;
    C += (long)blockIdx.z * sC;
    const int tid = threadIdx.x;
    const int warp = tid >> 5, lane = tid & 31;
    const int wm = warp & 1, wn = warp >> 1;          // 2 x 2 warp grid
    const int m0w = wm * 64, n0w = wn * 64;
    const int g = lane >> 2, t = lane & 3;

    const int ar   = lane & 15;
    const int asel = (lane >> 4) * 4;
    const int br   = (lane & 7) + ((lane >> 4) << 3);
    const int bsel = ((lane >> 3) & 1) * 4;

    float acc[4][8][4];
#pragma unroll
    for (int i = 0; i < 4; i++)
#pragma unroll
        for (int j = 0; j < 8; j++)
#pragma unroll
            for (int r = 0; r < 4; r++) acc[i][j][r] = 0.f;

    const int KT = Keff / BK;

    auto load_stage = [&](int st, int k0) {
#pragma unroll
        for (int c = tid; c < 512; c += 128) {
            int row = c >> 2, kc = (c & 3) * 4;
            uint32_t d = smem_u32(&As[st][row][kc]);
            cpa16(d, A + (long)(m0 + row) * lda + k0 + kc, true);
        }
        if (!TB) {
#pragma unroll
            for (int c = tid; c < 512; c += 128) {
                int row = c >> 5, col = (c & 31) * 4;
                bool v = (n0 + col) < N;
                uint32_t d = smem_u32(&Bs[st][row][col]);
                cpa16(d, B + (long)(k0 + row) * ldb + n0 + col, v);
            }
        } else {
#pragma unroll
            for (int c = tid; c < 512; c += 128) {
                int row = c >> 2, kc = (c & 3) * 4;
                bool v = (n0 + row) < N;
                uint32_t d = smem_u32(&Bs[st][row][kc]);
                cpa16(d, B + (long)(n0 + row) * ldb + k0 + kc, v);
            }
        }
        cpa_commit();
    };

    load_stage(0, 0);
    if (KT > 1) load_stage(1, BK); else cpa_commit();
    if (KT > 2) load_stage(2, 2 * BK); else cpa_commit();

    for (int kt = 0; kt < KT; ++kt) {
        cpa_wait<2>();
        __syncthreads();
        if (kt + 3 < KT) load_stage((kt + 3) & 3, (kt + 3) * BK);
        else cpa_commit();
        const int st = kt & 3;

#pragma unroll
        for (int ks = 0; ks < 2; ks++) {
            const int kk = ks * 8;
            uint32_t af[4][4], bf[8][2];
#pragma unroll
            for (int mt = 0; mt < 4; mt++) {
                ldm4(af[mt][0], af[mt][1], af[mt][2], af[mt][3],
                     smem_u32(&As[st][m0w + mt * 16 + ar][kk + asel]));
            }
            if (TB) {
#pragma unroll
                for (int ntp = 0; ntp < 4; ntp++) {
                    ldm4(bf[2 * ntp][0], bf[2 * ntp][1],
                         bf[2 * ntp + 1][0], bf[2 * ntp + 1][1],
                         smem_u32(&Bs[st][n0w + ntp * 16 + br][kk + bsel]));
                }
            } else {
#pragma unroll
                for (int nt = 0; nt < 8; nt++) {
                    const int nc = n0w + nt * 8 + g;
                    bf[nt][0] = __float_as_uint(Bs[st][kk + t][nc]);
                    bf[nt][1] = __float_as_uint(Bs[st][kk + t + 4][nc]);
                }
            }
#pragma unroll
            for (int mt = 0; mt < 4; mt++)
#pragma unroll
                for (int nt = 0; nt < 8; nt++)
                    mma_tf32(acc[mt][nt], af[mt][0], af[mt][1], af[mt][2], af[mt][3],
                             bf[nt][0], bf[nt][1]);
        }
    }

    // epilogue
#pragma unroll
    for (int mt = 0; mt < 4; mt++) {
        const int mr = m0 + m0w + mt * 16 + g;
        float* Cp0 = C + (long)mr * ldc;
        float* Cp1 = C + (long)(mr + 8) * ldc;
#pragma unroll
        for (int nt = 0; nt < 8; nt++) {
            int gn = n0 + n0w + nt * 8 + t * 2;
            if (gn < N) {
                float4 v = make_float4(acc[mt][nt][0], acc[mt][nt][1],
                                       acc[mt][nt][2], acc[mt][nt][3]);
                if (RND) { v.x = rtf(v.x); v.y = rtf(v.y); v.z = rtf(v.z); v.w = rtf(v.w); }
                *reinterpret_cast<float2*>(Cp0 + gn) = make_float2(v.x, v.y);
                *reinterpret_cast<float2*>(Cp1 + gn) = make_float2(v.z, v.w);
            }
        }
    }
}

// ---------------------------------------------------------------------------
template <bool IS_MAX>
__device__ __forceinline__ float block_reduce(float v, float* sh)
{
    __syncthreads();
#pragma unroll
    for (int o = 16; o; o >>= 1) {
        float t = __shfl_xor_sync(0xffffffffu, v, o);
        v = IS_MAX ? fmaxf(v, t) : v + t;
    }
    const int lane = threadIdx.x & 31, w = threadIdx.x >> 5;
    if (lane == 0) sh[w] = v;
    __syncthreads();
    const int nw = blockDim.x >> 5;
    if (w == 0) {
        v = (lane < nw) ? sh[lane] : (IS_MAX ? -INFINITY : 0.f);
#pragma unroll
        for (int o = 16; o; o >>= 1) {
            float t = __shfl_xor_sync(0xffffffffu, v, o);
            v = IS_MAX ? fmaxf(v, t) : v + t;
        }
        if (lane == 0) sh[0] = v;
    }
    __syncthreads();
    return sh[0];
}

__global__ void rmsnorm_kernel(const float* __restrict__ in, const float* __restrict__ w,
                               float* __restrict__ out, int width, int ldin, int ldout)
{
    __shared__ float sh[32];
    const long row = blockIdx.x;
    const float* x = in + row * ldin;
    float* y = out + row * ldout;
    float ss = 0.f;
    for (int i = threadIdx.x; i < width; i += blockDim.x) {
        float v = x[i];
        ss += v * v;
    }
    float tot = block_reduce<false>(ss, sh);
    float rinv = rsqrtf(tot / (float)width + 1e-6f);
    for (int i = threadIdx.x; i < width; i += blockDim.x)
        y[i] = rtf(x[i] * rinv * w[i]);
}

// rope for k_pe: qkv[t, 2048:2112] -> kf[t, 512:576]
__global__ void rope_k(const float* __restrict__ qkv, const float* __restrict__ fc,
                       float* __restrict__ kf)
{
    int idx = blockIdx.x * blockDim.x + threadIdx.x;
    int t = idx >> 5, i = idx & 31;
    int pos = t & 1023;
    float c = fc[(pos * 32 + i) * 2 + 0];
    float s = fc[(pos * 32 + i) * 2 + 1];
    float xe = qkv[(long)t * 2112 + 2048 + 2 * i];
    float xo = qkv[(long)t * 2112 + 2049 + 2 * i];
    kf[(long)t * 576 + 512 + 2 * i] = rtf(xe * c - xo * s);
    kf[(long)t * 576 + 513 + 2 * i] = rtf(xe * s + xo * c);
}

__global__ void rope_q(const float* __restrict__ q, const float* __restrict__ fc,
                       float* __restrict__ qf)
{
    long idx = (long)blockIdx.x * blockDim.x + threadIdx.x;
    int i = idx & 31;
    int h = (idx >> 5) & 31;
    long r = idx >> 10;
    int pos = (int)(r & 1023);
    const float* src = q + r * 6144 + h * 192 + 128 + 2 * i;
    float xe = src[0], xo = src[1];
    float c = fc[(pos * 32 + i) * 2 + 0];
    float s = fc[(pos * 32 + i) * 2 + 1];
    float* dst = qf + (r * 32 + h) * 576 + 512 + 2 * i;
    dst[0] = rtf(xe * c - xo * s);
    dst[1] = rtf(xe * s + xo * c);
}

// softmax: one block per (b,s); 32 rows (heads), 8 threads/row.
__global__ __launch_bounds__(256) void softmax_kernel(float* __restrict__ sc,
                                                      const float* __restrict__ mask)
{
    const int bs = blockIdx.x;
    const int b = bs >> 10, s = bs & 1023;
    const int W = ((s & ~3) + 19) & ~15;
    const int r = threadIdx.x >> 3;
    const int t = threadIdx.x & 7;
    float* p = sc + ((long)b * 32768 + s * 32 + r) * 1024;
    const float* mk = mask + (long)s * 1024;
    const float scale = 0.07216878364870322f;

    float mx = -INFINITY;
    for (int j = t; j < W; j += 8)
        mx = fmaxf(mx, p[j] * scale + mk[j]);
#pragma unroll
    for (int o = 4; o; o >>= 1)
        mx = fmaxf(mx, __shfl_xor_sync(0xffffffffu, mx, o));

    float sum = 0.f;
    for (int j = t; j < W; j += 8) {
        float e = expf(p[j] * scale + mk[j] - mx);
        p[j] = e;
        sum += e;
    }
#pragma unroll
    for (int o = 4; o; o >>= 1)
        sum += __shfl_xor_sync(0xffffffffu, sum, o);
    float inv = 1.f / sum;
    for (int j = t; j < W; j += 8)
        p[j] = rtf(p[j] * inv);
}

// ---------------------------------------------------------------------------
extern "C" void kernel_launch(void* const* d_in, const int* in_sizes, int n_in,
                              void* d_out, int out_size)
{
    const float* x        = (const float*)d_in[0];
    const float* fc       = (const float*)d_in[1];
    const float* mask     = (const float*)d_in[2];
    const float* wq_a     = (const float*)d_in[3];
    const float* q_norm_w = (const float*)d_in[4];
    const float* wq_b     = (const float*)d_in[5];
    const float* wkv_a    = (const float*)d_in[6];
    const float* kv_norm_w= (const float*)d_in[7];
    const float* wkv_b    = (const float*)d_in[8];
    const float* wo       = (const float*)d_in[9];
    float* out = (float*)d_out;

    float *qkv, *qa, *q, *kf, *qf, *sc, *oc, *ov;
    float *xr, *w13, *w2, *w4, *w5;
    cudaGetSymbolAddress((void**)&qkv, g_qkv);
    cudaGetSymbolAddress((void**)&qa, g_qa);
    cudaGetSymbolAddress((void**)&q,  g_q);
    cudaGetSymbolAddress((void**)&kf, g_kf);
    cudaGetSymbolAddress((void**)&qf, g_qf);
    cudaGetSymbolAddress((void**)&sc, g_sc);
    cudaGetSymbolAddress((void**)&oc, g_oc);
    cudaGetSymbolAddress((void**)&ov, g_ov);
    cudaGetSymbolAddress((void**)&xr, g_xr);
    cudaGetSymbolAddress((void**)&w13, g_w13);
    cudaGetSymbolAddress((void**)&w2, g_w2);
    cudaGetSymbolAddress((void**)&w4, g_w4);
    cudaGetSymbolAddress((void**)&w5, g_w5);

    const int SM_NT = STAGES * (BM * (BK + PAD) + BK * (BN + BPAD_NT)) * 4;
    const int SM_TB = STAGES * (BM * (BK + PAD) + BN * (BK + PAD)) * 4;
    cudaFuncSetAttribute(gemm_tc<false, false, false, false>,
                         cudaFuncAttributeMaxDynamicSharedMemorySize, SM_NT);
    cudaFuncSetAttribute(gemm_tc<false, false, false, true>,
                         cudaFuncAttributeMaxDynamicSharedMemorySize, SM_NT);
    cudaFuncSetAttribute(gemm_tc<true, true, false, false>,
                         cudaFuncAttributeMaxDynamicSharedMemorySize, SM_TB);
    cudaFuncSetAttribute(gemm_tc<false, false, true, true>,
                         cudaFuncAttributeMaxDynamicSharedMemorySize, SM_NT);
    cudaFuncSetAttribute(gemm_tc<true, false, false, true>,
                         cudaFuncAttributeMaxDynamicSharedMemorySize, SM_TB);

    const dim3 blk(128);

    // 0. tf32-round inputs
    {
        long n4 = 2048L * 4096 / 4;
        round_tf32<<<(int)((n4 + 255) / 256), 256>>>(x, xr, n4);
        n4 = 1536L * 6144 / 4;
        round_tf32<<<(int)((n4 + 255) / 256), 256>>>(wq_b, w2, n4);
        n4 = 32L * 256 * 512 / 4;
        round_tf32<<<(int)((n4 + 255) / 256), 256>>>(wkv_b, w4, n4);
        n4 = 4096L * 4096 / 4;
        round_tf32<<<(int)((n4 + 255) / 256), 256>>>(wo, w5, n4);
        n4 = 4096L * 1536 / 4;
        round_tf32_str<<<(int)((n4 + 255) / 256), 256>>>(wq_a, w13, 4096, 1536, 2112, 0);
        n4 = 4096L * 576 / 4;
        round_tf32_str<<<(int)((n4 + 255) / 256), 256>>>(wkv_a, w13, 4096, 576, 2112, 1536);
    }

    // 1. qkv = x @ [wq_a | wkv_a]
    gemm_tc<false, false, false, false><<<dim3(17, 16, 1), blk, SM_NT>>>(
        xr, w13, qkv, 2048, 2112, 4096, 4096, 2112, 2112, 0, 0, 0);
    // 2. qa = rmsnorm(qkv[:, :1536])
    rmsnorm_kernel<<<2048, 256>>>(qkv, q_norm_w, qa, 1536, 2112, 1536);
    // 3. q = qa @ wq_b
    gemm_tc<false, false, false, true><<<dim3(48, 16, 1), blk, SM_NT>>>(
        qa, w2, q, 2048, 6144, 1536, 1536, 6144, 6144, 0, 0, 0);
    // 5. kf
    rmsnorm_kernel<<<2048, 256>>>(qkv + 1536, kv_norm_w, kf, 512, 2112, 576);
    rope_k<<<256, 256>>>(qkv, fc, kf);
    // 6. q_pe rope
    rope_q<<<2048, 1024>>>(q, fc, qf);
    // 7. q absorb (z = h)
    gemm_tc<false, false, false, true><<<dim3(4, 16, 32), blk, SM_NT>>>(
        q, w4, qf, 2048, 512, 128, 6144, 512, 32 * 576,
        192, 256L * 512, 576);
    // 8. scores (z = b, TB, causal skip)
    gemm_tc<true, true, false, false><<<dim3(8, 256, 2), blk, SM_TB>>>(
        qf, kf, sc, 32768, 1024, 576, 576, 576, 1024,
        32768L * 576, 1024L * 576, 32768L * 1024);
    // 9. softmax
    softmax_kernel<<<2048, 256>>>(sc, mask);
    // 10. PV (z = b, causal K clamp)
    gemm_tc<false, false, true, true><<<dim3(4, 256, 2), blk, SM_NT>>>(
        sc, kf, oc, 32768, 512, 1024, 1024, 576, 512,
        32768L * 1024, 1024L * 576, 32768L * 512);
    // 11. v proj (z = h, TB)
    gemm_tc<true, false, false, true><<<dim3(1, 16, 32), blk, SM_TB>>>(
        oc, w4 + 128 * 512, ov, 2048, 128, 512, 32 * 512, 512, 4096,
        512, 256L * 512, 128);
    // 12. out = ov @ wo
    gemm_tc<false, false, false, false><<<dim3(32, 16, 1), blk, SM_NT>>>(
        ov, w5, out, 2048, 4096, 4096, 4096, 4096, 4096, 0, 0, 0);
}